// round 4
// baseline (speedup 1.0000x reference)
#include <cuda_runtime.h>
#include <cuda_bf16.h>
#include <mma.h>
#include <math.h>
#include <stdint.h>

using namespace nvcuda;

#define BATCH 4
#define TSEQ  4096
#define DMODEL 1024
#define HDIM  64
#define NROWS (BATCH*TSEQ)

#define SCALE_Q 0.18033688011112042f   // log2(e)/8

// Scratch (device globals — no allocations allowed)
__device__ float g_q[NROWS*HDIM];
__device__ float g_k[NROWS*HDIM];
__device__ float g_v[NROWS*HDIM];
__device__ float g_rowsum[NROWS];
__device__ float g_ent;

__global__ void zero_kernel() { g_ent = 0.0f; }

__device__ __forceinline__ float ex2f_(float x){ float y; asm("ex2.approx.ftz.f32 %0, %1;" : "=f"(y) : "f"(x)); return y; }
__device__ __forceinline__ float lg2f_(float x){ float y; asm("lg2.approx.f32 %0, %1;" : "=f"(y) : "f"(x)); return y; }

__device__ __forceinline__ uint32_t pk2(float a, float b){
    __nv_bfloat162 t; t.x = __float2bfloat16(a); t.y = __float2bfloat16(b);
    return *reinterpret_cast<uint32_t*>(&t);
}
__device__ __forceinline__ float bflo(float f){
    return f - __bfloat162float(__float2bfloat16(f));
}

typedef wmma::fragment<wmma::matrix_a, 16,16,16, __nv_bfloat16, wmma::row_major> FragA;
typedef wmma::fragment<wmma::matrix_b, 16,16,16, __nv_bfloat16, wmma::col_major> FragBc;
typedef wmma::fragment<wmma::matrix_b, 16,16,16, __nv_bfloat16, wmma::row_major> FragBr;
typedef wmma::fragment<wmma::accumulator, 16,16,16, float> FragC;

// ---------------------------------------------------------------------------
// K1: QKV projection via wmma bf16 hi/lo split.
// grid (NROWS/128, 3), 256 threads. CTA: 128 rows x 64 out cols.
// ---------------------------------------------------------------------------
__global__ __launch_bounds__(256, 1) void proj_kernel(
    const float* __restrict__ x,
    const float* __restrict__ Wq,
    const float* __restrict__ Wk,
    const float* __restrict__ Wv)
{
    __shared__ __nv_bfloat16 xhi[128*64], xlo[128*64];   // 32KB
    __shared__ __nv_bfloat16 whi[64*64],  wlo[64*64];    // 16KB

    const float* W   = (blockIdx.y == 0) ? Wq : ((blockIdx.y == 1) ? Wk : Wv);
    float*       out = (blockIdx.y == 0) ? g_q : ((blockIdx.y == 1) ? g_k : g_v);

    const int row0 = blockIdx.x * 128;
    const int tid  = threadIdx.x;
    const int w    = tid >> 5;

    FragC acc[4];
    #pragma unroll
    for (int n = 0; n < 4; n++) wmma::fill_fragment(acc[n], 0.0f);

    for (int c0 = 0; c0 < DMODEL; c0 += 64) {
        __syncthreads();
        #pragma unroll
        for (int i = 0; i < 16; i++) {            // x chunk 128x64
            int p = i*256 + tid;
            int r = p >> 5, c2 = p & 31;
            float2 v = *(const float2*)&x[(size_t)(row0 + r)*DMODEL + c0 + 2*c2];
            ((uint32_t*)xhi)[r*32 + c2] = pk2(v.x, v.y);
            ((uint32_t*)xlo)[r*32 + c2] = pk2(bflo(v.x), bflo(v.y));
        }
        #pragma unroll
        for (int i = 0; i < 8; i++) {             // W chunk 64x64
            int p = i*256 + tid;
            int h = p >> 5, c2 = p & 31;
            float2 v = *(const float2*)&W[(size_t)h*DMODEL + c0 + 2*c2];
            ((uint32_t*)whi)[h*32 + c2] = pk2(v.x, v.y);
            ((uint32_t*)wlo)[h*32 + c2] = pk2(bflo(v.x), bflo(v.y));
        }
        __syncthreads();
        #pragma unroll
        for (int t = 0; t < 3; t++) {
            const __nv_bfloat16* A = (t == 2) ? xlo : xhi;
            const __nv_bfloat16* B = (t == 1) ? wlo : whi;
            #pragma unroll
            for (int kk = 0; kk < 4; kk++) {
                FragA af;
                wmma::load_matrix_sync(af, A + (16*w)*64 + kk*16, 64);
                #pragma unroll
                for (int n = 0; n < 4; n++) {
                    FragBc bf;
                    wmma::load_matrix_sync(bf, B + (n*16)*64 + kk*16, 64);
                    wmma::mma_sync(acc[n], af, bf, acc[n]);
                }
            }
        }
    }
    #pragma unroll
    for (int n = 0; n < 4; n++)
        wmma::store_matrix_sync(out + (size_t)(row0 + 16*w)*HDIM + n*16, acc[n], HDIM, wmma::mem_row_major);
}

// ---------------------------------------------------------------------------
// K2: fused attention pass 1 (wmma).  Per CTA: 128 q-rows x 4096 keys.
// Writes unnormalized E to attn, rowsums Z, entropy partials, out = (E@V)/Z.
// ---------------------------------------------------------------------------
// dynamic smem layout (bytes)
#define OQHI 0
#define OQLO 16384
#define OKHI 32768
#define OKLO 49152
#define OVHI 65536
#define OVLO 81920
#define OSB  98304            // per-warp fp32 strips 16x128 (8KB each, 64KB)
#define OPHI 163840           // E hi bf16 [128][128]  32KB
#define OPLO 196608           // E lo bf16 [128][128]  32KB
#define SMEM_DYN 229376

__global__ __launch_bounds__(256, 1) void attn1_kernel(float* __restrict__ attn,
                                                       float* __restrict__ out)
{
    extern __shared__ char sm[];
    __nv_bfloat16* qhi = (__nv_bfloat16*)(sm + OQHI);
    __nv_bfloat16* qlo = (__nv_bfloat16*)(sm + OQLO);
    __nv_bfloat16* khi = (__nv_bfloat16*)(sm + OKHI);
    __nv_bfloat16* klo = (__nv_bfloat16*)(sm + OKLO);
    __nv_bfloat16* vhi = (__nv_bfloat16*)(sm + OVHI);
    __nv_bfloat16* vlo = (__nv_bfloat16*)(sm + OVLO);
    __nv_bfloat16* phi = (__nv_bfloat16*)(sm + OPHI);
    __nv_bfloat16* plo = (__nv_bfloat16*)(sm + OPLO);
    __shared__ float s_ent[8];

    const int tid  = threadIdx.x;
    const int w    = tid >> 5;
    const int lane = tid & 31;
    const int b    = blockIdx.y;
    const int q0   = blockIdx.x * 128;
    const size_t rowg0 = (size_t)b*TSEQ + q0 + 16*w;   // this warp's first global row

    float* Sw = (float*)(sm + OSB) + w*16*128;         // warp-private strip

    // Q load + scale + split (once)
    {
        const float* Qg = g_q + ((size_t)b*TSEQ + q0)*HDIM;
        #pragma unroll
        for (int i = 0; i < 16; i++) {
            int p = i*256 + tid;
            int r = p >> 5, c2 = p & 31;
            float2 v = *(const float2*)&Qg[(size_t)r*HDIM + 2*c2];
            v.x *= SCALE_Q; v.y *= SCALE_Q;
            ((uint32_t*)qhi)[r*32 + c2] = pk2(v.x, v.y);
            ((uint32_t*)qlo)[r*32 + c2] = pk2(bflo(v.x), bflo(v.y));
        }
    }

    FragC oacc[4];
    #pragma unroll
    for (int n = 0; n < 4; n++) wmma::fill_fragment(oacc[n], 0.0f);

    float Zacc[16], Eacc[16];
    #pragma unroll
    for (int r = 0; r < 16; r++) { Zacc[r] = 0.0f; Eacc[r] = 0.0f; }

    for (int c = 0; c < TSEQ/128; c++) {
        const float* Kg = g_k + ((size_t)b*TSEQ + c*128)*HDIM;
        const float* Vg = g_v + ((size_t)b*TSEQ + c*128)*HDIM;
        __syncthreads();
        #pragma unroll
        for (int i = 0; i < 16; i++) {            // K chunk 128x64
            int p = i*256 + tid;
            int r = p >> 5, c2 = p & 31;
            float2 v = *(const float2*)&Kg[(size_t)r*HDIM + 2*c2];
            ((uint32_t*)khi)[r*32 + c2] = pk2(v.x, v.y);
            ((uint32_t*)klo)[r*32 + c2] = pk2(bflo(v.x), bflo(v.y));
        }
        #pragma unroll
        for (int i = 0; i < 16; i++) {            // V chunk 128x64
            int p = i*256 + tid;
            int r = p >> 5, c2 = p & 31;
            float2 v = *(const float2*)&Vg[(size_t)r*HDIM + 2*c2];
            ((uint32_t*)vhi)[r*32 + c2] = pk2(v.x, v.y);
            ((uint32_t*)vlo)[r*32 + c2] = pk2(bflo(v.x), bflo(v.y));
        }
        __syncthreads();

        // S = Q K^T  (16-row strip x 128 cols per warp)
        FragC sacc[8];
        #pragma unroll
        for (int n = 0; n < 8; n++) wmma::fill_fragment(sacc[n], 0.0f);
        #pragma unroll
        for (int t = 0; t < 3; t++) {
            const __nv_bfloat16* A = (t == 2) ? qlo : qhi;
            const __nv_bfloat16* B = (t == 1) ? klo : khi;
            #pragma unroll
            for (int kk = 0; kk < 4; kk++) {
                FragA af;
                wmma::load_matrix_sync(af, A + (16*w)*64 + kk*16, 64);
                #pragma unroll
                for (int n = 0; n < 8; n++) {
                    FragBc bf;
                    wmma::load_matrix_sync(bf, B + (n*16)*64 + kk*16, 64);
                    wmma::mma_sync(sacc[n], af, bf, sacc[n]);
                }
            }
        }
        #pragma unroll
        for (int n = 0; n < 8; n++)
            wmma::store_matrix_sync(Sw + n*16, sacc[n], 128, wmma::mem_row_major);
        __syncwarp();

        // exp, rowsum, entropy, write E, stage E hi/lo for PV
        float* abase = attn + rowg0*TSEQ + c*128 + 4*lane;
        #pragma unroll
        for (int r = 0; r < 16; r++) {
            float4 s4 = *(const float4*)(Sw + r*128 + 4*lane);
            float e0 = ex2f_(s4.x), e1 = ex2f_(s4.y), e2 = ex2f_(s4.z), e3 = ex2f_(s4.w);
            Zacc[r] += (e0 + e1) + (e2 + e3);
            Eacc[r] += (e0*s4.x + e1*s4.y) + (e2*s4.z + e3*s4.w);
            *(float4*)(abase + (size_t)r*TSEQ) = make_float4(e0, e1, e2, e3);
            ((uint32_t*)phi)[(16*w + r)*64 + 2*lane]     = pk2(e0, e1);
            ((uint32_t*)phi)[(16*w + r)*64 + 2*lane + 1] = pk2(e2, e3);
            ((uint32_t*)plo)[(16*w + r)*64 + 2*lane]     = pk2(bflo(e0), bflo(e1));
            ((uint32_t*)plo)[(16*w + r)*64 + 2*lane + 1] = pk2(bflo(e2), bflo(e3));
        }
        __syncwarp();

        // O += E V
        #pragma unroll
        for (int t = 0; t < 3; t++) {
            const __nv_bfloat16* A = (t == 2) ? plo : phi;
            const __nv_bfloat16* B = (t == 1) ? vlo : vhi;
            #pragma unroll
            for (int kk = 0; kk < 8; kk++) {
                FragA af;
                wmma::load_matrix_sync(af, A + (16*w)*128 + kk*16, 128);
                #pragma unroll
                for (int n = 0; n < 4; n++) {
                    FragBr bf;
                    wmma::load_matrix_sync(bf, B + (kk*16)*64 + n*16, 64);
                    wmma::mma_sync(oacc[n], af, bf, oacc[n]);
                }
            }
        }
    }

    // per-row reductions across lanes
    float myZ = 1.0f, myS = 0.0f;
    #pragma unroll
    for (int r = 0; r < 16; r++) {
        float z = Zacc[r], s = Eacc[r];
        #pragma unroll
        for (int off = 16; off > 0; off >>= 1) {
            z += __shfl_xor_sync(0xffffffffu, z, off);
            s += __shfl_xor_sync(0xffffffffu, s, off);
        }
        if (lane == r) { myZ = z; myS = s; }
    }
    if (lane < 16) g_rowsum[rowg0 + lane] = myZ;

    // entropy partial: H/ln2 = lg2(Z) - S/Z per row
    float h = (lane < 16) ? (lg2f_(myZ) - myS/myZ) : 0.0f;
    #pragma unroll
    for (int off = 16; off > 0; off >>= 1) h += __shfl_xor_sync(0xffffffffu, h, off);
    if (lane == 0) s_ent[w] = h;

    // O strip -> smem -> scale by 1/Z -> gmem
    __syncwarp();
    #pragma unroll
    for (int n = 0; n < 4; n++)
        wmma::store_matrix_sync(Sw + n*16, oacc[n], 64, wmma::mem_row_major);
    __syncwarp();
    float* obase = out + rowg0*HDIM + 2*lane;
    #pragma unroll
    for (int r = 0; r < 16; r++) {
        float zr = __shfl_sync(0xffffffffu, myZ, r);
        float inv = __fdividef(1.0f, zr);
        float2 v = *(const float2*)(Sw + r*64 + 2*lane);
        v.x *= inv; v.y *= inv;
        *(float2*)(obase + (size_t)r*HDIM) = v;
    }

    __syncthreads();
    if (tid == 0) {
        float t = 0.0f;
        #pragma unroll
        for (int i = 0; i < 8; i++) t += s_ent[i];
        atomicAdd(&g_ent, t);
    }
}

// ---------------------------------------------------------------------------
// K3: normalize attn rows in place:  P = E / Z
// ---------------------------------------------------------------------------
__global__ __launch_bounds__(256) void norm_kernel(float* __restrict__ attn)
{
    const size_t row = blockIdx.x;
    const float inv = 1.0f / g_rowsum[row];
    float4* p = (float4*)(attn + row*TSEQ);
    const int tid = threadIdx.x;
    #pragma unroll
    for (int j = 0; j < 4; j++) {
        int idx = tid + j*256;
        float4 v = p[idx];
        v.x *= inv; v.y *= inv; v.z *= inv; v.w *= inv;
        p[idx] = v;
    }
}

// ---------------------------------------------------------------------------
// K4: finalize energy EMA.  H_mean = ln2 * g_ent / NROWS
// ---------------------------------------------------------------------------
__global__ void fin_kernel(const float* __restrict__ energy, float* __restrict__ eout)
{
    float ent_mean = 0.6931471805599453f * g_ent / (float)NROWS;
    *eout = 0.9f * energy[0] + 0.1f * ent_mean;
}

// ---------------------------------------------------------------------------
extern "C" void kernel_launch(void* const* d_in, const int* in_sizes, int n_in,
                              void* d_out, int out_size)
{
    const float* x      = (const float*)d_in[0];
    const float* Wq     = (const float*)d_in[1];
    const float* Wk     = (const float*)d_in[2];
    const float* Wv     = (const float*)d_in[3];
    const float* energy = (const float*)d_in[4];

    float* out  = (float*)d_out;                               // [B,T,H]
    float* attn = out + (size_t)BATCH*TSEQ*HDIM;               // [B,T,T]
    float* eout = attn + (size_t)BATCH*TSEQ*TSEQ;              // scalar

    cudaFuncSetAttribute(attn1_kernel, cudaFuncAttributeMaxDynamicSharedMemorySize, SMEM_DYN);

    zero_kernel<<<1, 1>>>();
    proj_kernel<<<dim3(NROWS/128, 3), 256>>>(x, Wq, Wk, Wv);
    attn1_kernel<<<dim3(TSEQ/128, BATCH), 256, SMEM_DYN>>>(attn, out);
    norm_kernel<<<NROWS, 256>>>(attn);
    fin_kernel<<<1, 1>>>(energy, eout);
}

// round 5
// speedup vs baseline: 1.0010x; 1.0010x over previous
#include <cuda_runtime.h>
#include <cuda_bf16.h>
#include <mma.h>
#include <math.h>
#include <stdint.h>

using namespace nvcuda;

#define BATCH 4
#define TSEQ  4096
#define DMODEL 1024
#define HDIM  64
#define NROWS (BATCH*TSEQ)

#define SCALE_Q 0.18033688011112042f   // log2(e)/8

// Scratch (device globals — no allocations allowed)
__device__ float g_q[NROWS*HDIM];
__device__ float g_k[NROWS*HDIM];
__device__ float g_v[NROWS*HDIM];
__device__ float g_rowsum[NROWS];
__device__ float g_ent;

__global__ void zero_kernel() { g_ent = 0.0f; }

__device__ __forceinline__ float ex2f_(float x){ float y; asm("ex2.approx.ftz.f32 %0, %1;" : "=f"(y) : "f"(x)); return y; }
__device__ __forceinline__ float lg2f_(float x){ float y; asm("lg2.approx.f32 %0, %1;" : "=f"(y) : "f"(x)); return y; }

__device__ __forceinline__ uint32_t pk2(float a, float b){
    __nv_bfloat162 t; t.x = __float2bfloat16(a); t.y = __float2bfloat16(b);
    return *reinterpret_cast<uint32_t*>(&t);
}
__device__ __forceinline__ float bflo(float f){
    return f - __bfloat162float(__float2bfloat16(f));
}

typedef wmma::fragment<wmma::matrix_a, 16,16,16, __nv_bfloat16, wmma::row_major> FragA;
typedef wmma::fragment<wmma::matrix_b, 16,16,16, __nv_bfloat16, wmma::col_major> FragBc;
typedef wmma::fragment<wmma::matrix_b, 16,16,16, __nv_bfloat16, wmma::row_major> FragBr;
typedef wmma::fragment<wmma::accumulator, 16,16,16, float> FragC;

// ---------------------------------------------------------------------------
// K1: QKV projection via wmma bf16 hi/lo split.
// grid (NROWS/128, 3), 256 threads. CTA: 128 rows x 64 out cols.
// ---------------------------------------------------------------------------
__global__ __launch_bounds__(256, 1) void proj_kernel(
    const float* __restrict__ x,
    const float* __restrict__ Wq,
    const float* __restrict__ Wk,
    const float* __restrict__ Wv)
{
    __shared__ __nv_bfloat16 xhi[128*64], xlo[128*64];   // 32KB
    __shared__ __nv_bfloat16 whi[64*64],  wlo[64*64];    // 16KB

    const float* W   = (blockIdx.y == 0) ? Wq : ((blockIdx.y == 1) ? Wk : Wv);
    float*       out = (blockIdx.y == 0) ? g_q : ((blockIdx.y == 1) ? g_k : g_v);

    const int row0 = blockIdx.x * 128;
    const int tid  = threadIdx.x;
    const int w    = tid >> 5;

    FragC acc[4];
    #pragma unroll
    for (int n = 0; n < 4; n++) wmma::fill_fragment(acc[n], 0.0f);

    for (int c0 = 0; c0 < DMODEL; c0 += 64) {
        __syncthreads();
        #pragma unroll
        for (int i = 0; i < 16; i++) {            // x chunk 128x64
            int p = i*256 + tid;
            int r = p >> 5, c2 = p & 31;
            float2 v = *(const float2*)&x[(size_t)(row0 + r)*DMODEL + c0 + 2*c2];
            ((uint32_t*)xhi)[r*32 + c2] = pk2(v.x, v.y);
            ((uint32_t*)xlo)[r*32 + c2] = pk2(bflo(v.x), bflo(v.y));
        }
        #pragma unroll
        for (int i = 0; i < 8; i++) {             // W chunk 64x64
            int p = i*256 + tid;
            int h = p >> 5, c2 = p & 31;
            float2 v = *(const float2*)&W[(size_t)h*DMODEL + c0 + 2*c2];
            ((uint32_t*)whi)[h*32 + c2] = pk2(v.x, v.y);
            ((uint32_t*)wlo)[h*32 + c2] = pk2(bflo(v.x), bflo(v.y));
        }
        __syncthreads();
        #pragma unroll
        for (int t = 0; t < 3; t++) {
            const __nv_bfloat16* A = (t == 2) ? xlo : xhi;
            const __nv_bfloat16* B = (t == 1) ? wlo : whi;
            #pragma unroll
            for (int kk = 0; kk < 4; kk++) {
                FragA af;
                wmma::load_matrix_sync(af, A + (16*w)*64 + kk*16, 64);
                #pragma unroll
                for (int n = 0; n < 4; n++) {
                    FragBc bf;
                    wmma::load_matrix_sync(bf, B + (n*16)*64 + kk*16, 64);
                    wmma::mma_sync(acc[n], af, bf, acc[n]);
                }
            }
        }
    }
    #pragma unroll
    for (int n = 0; n < 4; n++)
        wmma::store_matrix_sync(out + (size_t)(row0 + 16*w)*HDIM + n*16, acc[n], HDIM, wmma::mem_row_major);
}

// ---------------------------------------------------------------------------
// K2: fused attention pass 1 (wmma).  Per CTA: 128 q-rows x 4096 keys.
// Writes unnormalized E to attn, rowsums Z, entropy partials, out = (E@V)/Z.
// ---------------------------------------------------------------------------
// dynamic smem layout (bytes)
#define OQHI 0
#define OQLO 16384
#define OKHI 32768
#define OKLO 49152
#define OVHI 65536
#define OVLO 81920
#define OSB  98304            // per-warp fp32 strips 16x128 (8KB each, 64KB)
#define OPHI 163840           // E hi bf16 [128][128]  32KB
#define OPLO 196608           // E lo bf16 [128][128]  32KB
#define SMEM_DYN 229376

__global__ __launch_bounds__(256, 1) void attn1_kernel(float* __restrict__ attn,
                                                       float* __restrict__ out)
{
    extern __shared__ char sm[];
    __nv_bfloat16* qhi = (__nv_bfloat16*)(sm + OQHI);
    __nv_bfloat16* qlo = (__nv_bfloat16*)(sm + OQLO);
    __nv_bfloat16* khi = (__nv_bfloat16*)(sm + OKHI);
    __nv_bfloat16* klo = (__nv_bfloat16*)(sm + OKLO);
    __nv_bfloat16* vhi = (__nv_bfloat16*)(sm + OVHI);
    __nv_bfloat16* vlo = (__nv_bfloat16*)(sm + OVLO);
    __nv_bfloat16* phi = (__nv_bfloat16*)(sm + OPHI);
    __nv_bfloat16* plo = (__nv_bfloat16*)(sm + OPLO);
    __shared__ float s_ent[8];

    const int tid  = threadIdx.x;
    const int w    = tid >> 5;
    const int lane = tid & 31;
    const int b    = blockIdx.y;
    const int q0   = blockIdx.x * 128;
    const size_t rowg0 = (size_t)b*TSEQ + q0 + 16*w;   // this warp's first global row

    float* Sw = (float*)(sm + OSB) + w*16*128;         // warp-private strip

    // Q load + scale + split (once)
    {
        const float* Qg = g_q + ((size_t)b*TSEQ + q0)*HDIM;
        #pragma unroll
        for (int i = 0; i < 16; i++) {
            int p = i*256 + tid;
            int r = p >> 5, c2 = p & 31;
            float2 v = *(const float2*)&Qg[(size_t)r*HDIM + 2*c2];
            v.x *= SCALE_Q; v.y *= SCALE_Q;
            ((uint32_t*)qhi)[r*32 + c2] = pk2(v.x, v.y);
            ((uint32_t*)qlo)[r*32 + c2] = pk2(bflo(v.x), bflo(v.y));
        }
    }

    FragC oacc[4];
    #pragma unroll
    for (int n = 0; n < 4; n++) wmma::fill_fragment(oacc[n], 0.0f);

    float Zacc[16], Eacc[16];
    #pragma unroll
    for (int r = 0; r < 16; r++) { Zacc[r] = 0.0f; Eacc[r] = 0.0f; }

    for (int c = 0; c < TSEQ/128; c++) {
        const float* Kg = g_k + ((size_t)b*TSEQ + c*128)*HDIM;
        const float* Vg = g_v + ((size_t)b*TSEQ + c*128)*HDIM;
        __syncthreads();
        #pragma unroll
        for (int i = 0; i < 16; i++) {            // K chunk 128x64
            int p = i*256 + tid;
            int r = p >> 5, c2 = p & 31;
            float2 v = *(const float2*)&Kg[(size_t)r*HDIM + 2*c2];
            ((uint32_t*)khi)[r*32 + c2] = pk2(v.x, v.y);
            ((uint32_t*)klo)[r*32 + c2] = pk2(bflo(v.x), bflo(v.y));
        }
        #pragma unroll
        for (int i = 0; i < 16; i++) {            // V chunk 128x64
            int p = i*256 + tid;
            int r = p >> 5, c2 = p & 31;
            float2 v = *(const float2*)&Vg[(size_t)r*HDIM + 2*c2];
            ((uint32_t*)vhi)[r*32 + c2] = pk2(v.x, v.y);
            ((uint32_t*)vlo)[r*32 + c2] = pk2(bflo(v.x), bflo(v.y));
        }
        __syncthreads();

        // S = Q K^T  (16-row strip x 128 cols per warp)
        FragC sacc[8];
        #pragma unroll
        for (int n = 0; n < 8; n++) wmma::fill_fragment(sacc[n], 0.0f);
        #pragma unroll
        for (int t = 0; t < 3; t++) {
            const __nv_bfloat16* A = (t == 2) ? qlo : qhi;
            const __nv_bfloat16* B = (t == 1) ? klo : khi;
            #pragma unroll
            for (int kk = 0; kk < 4; kk++) {
                FragA af;
                wmma::load_matrix_sync(af, A + (16*w)*64 + kk*16, 64);
                #pragma unroll
                for (int n = 0; n < 8; n++) {
                    FragBc bf;
                    wmma::load_matrix_sync(bf, B + (n*16)*64 + kk*16, 64);
                    wmma::mma_sync(sacc[n], af, bf, sacc[n]);
                }
            }
        }
        #pragma unroll
        for (int n = 0; n < 8; n++)
            wmma::store_matrix_sync(Sw + n*16, sacc[n], 128, wmma::mem_row_major);
        __syncwarp();

        // exp, rowsum, entropy, write E, stage E hi/lo for PV
        float* abase = attn + rowg0*TSEQ + c*128 + 4*lane;
        #pragma unroll
        for (int r = 0; r < 16; r++) {
            float4 s4 = *(const float4*)(Sw + r*128 + 4*lane);
            float e0 = ex2f_(s4.x), e1 = ex2f_(s4.y), e2 = ex2f_(s4.z), e3 = ex2f_(s4.w);
            Zacc[r] += (e0 + e1) + (e2 + e3);
            Eacc[r] += (e0*s4.x + e1*s4.y) + (e2*s4.z + e3*s4.w);
            *(float4*)(abase + (size_t)r*TSEQ) = make_float4(e0, e1, e2, e3);
            ((uint32_t*)phi)[(16*w + r)*64 + 2*lane]     = pk2(e0, e1);
            ((uint32_t*)phi)[(16*w + r)*64 + 2*lane + 1] = pk2(e2, e3);
            ((uint32_t*)plo)[(16*w + r)*64 + 2*lane]     = pk2(bflo(e0), bflo(e1));
            ((uint32_t*)plo)[(16*w + r)*64 + 2*lane + 1] = pk2(bflo(e2), bflo(e3));
        }
        __syncwarp();

        // O += E V
        #pragma unroll
        for (int t = 0; t < 3; t++) {
            const __nv_bfloat16* A = (t == 2) ? plo : phi;
            const __nv_bfloat16* B = (t == 1) ? vlo : vhi;
            #pragma unroll
            for (int kk = 0; kk < 8; kk++) {
                FragA af;
                wmma::load_matrix_sync(af, A + (16*w)*128 + kk*16, 128);
                #pragma unroll
                for (int n = 0; n < 4; n++) {
                    FragBr bf;
                    wmma::load_matrix_sync(bf, B + (kk*16)*64 + n*16, 64);
                    wmma::mma_sync(oacc[n], af, bf, oacc[n]);
                }
            }
        }
    }

    // per-row reductions across lanes
    float myZ = 1.0f, myS = 0.0f;
    #pragma unroll
    for (int r = 0; r < 16; r++) {
        float z = Zacc[r], s = Eacc[r];
        #pragma unroll
        for (int off = 16; off > 0; off >>= 1) {
            z += __shfl_xor_sync(0xffffffffu, z, off);
            s += __shfl_xor_sync(0xffffffffu, s, off);
        }
        if (lane == r) { myZ = z; myS = s; }
    }
    if (lane < 16) g_rowsum[rowg0 + lane] = myZ;

    // entropy partial: H/ln2 = lg2(Z) - S/Z per row
    float h = (lane < 16) ? (lg2f_(myZ) - myS/myZ) : 0.0f;
    #pragma unroll
    for (int off = 16; off > 0; off >>= 1) h += __shfl_xor_sync(0xffffffffu, h, off);
    if (lane == 0) s_ent[w] = h;

    // O strip -> smem -> scale by 1/Z -> gmem
    __syncwarp();
    #pragma unroll
    for (int n = 0; n < 4; n++)
        wmma::store_matrix_sync(Sw + n*16, oacc[n], 64, wmma::mem_row_major);
    __syncwarp();
    float* obase = out + rowg0*HDIM + 2*lane;
    #pragma unroll
    for (int r = 0; r < 16; r++) {
        float zr = __shfl_sync(0xffffffffu, myZ, r);
        float inv = __fdividef(1.0f, zr);
        float2 v = *(const float2*)(Sw + r*64 + 2*lane);
        v.x *= inv; v.y *= inv;
        *(float2*)(obase + (size_t)r*HDIM) = v;
    }

    __syncthreads();
    if (tid == 0) {
        float t = 0.0f;
        #pragma unroll
        for (int i = 0; i < 8; i++) t += s_ent[i];
        atomicAdd(&g_ent, t);
    }
}

// ---------------------------------------------------------------------------
// K3: normalize attn rows in place:  P = E / Z
// ---------------------------------------------------------------------------
__global__ __launch_bounds__(256) void norm_kernel(float* __restrict__ attn)
{
    const size_t row = blockIdx.x;
    const float inv = 1.0f / g_rowsum[row];
    float4* p = (float4*)(attn + row*TSEQ);
    const int tid = threadIdx.x;
    #pragma unroll
    for (int j = 0; j < 4; j++) {
        int idx = tid + j*256;
        float4 v = p[idx];
        v.x *= inv; v.y *= inv; v.z *= inv; v.w *= inv;
        p[idx] = v;
    }
}

// ---------------------------------------------------------------------------
// K4: finalize energy EMA.  H_mean = ln2 * g_ent / NROWS
// ---------------------------------------------------------------------------
__global__ void fin_kernel(const float* __restrict__ energy, float* __restrict__ eout)
{
    float ent_mean = 0.6931471805599453f * g_ent / (float)NROWS;
    *eout = 0.9f * energy[0] + 0.1f * ent_mean;
}

// ---------------------------------------------------------------------------
extern "C" void kernel_launch(void* const* d_in, const int* in_sizes, int n_in,
                              void* d_out, int out_size)
{
    const float* x      = (const float*)d_in[0];
    const float* Wq     = (const float*)d_in[1];
    const float* Wk     = (const float*)d_in[2];
    const float* Wv     = (const float*)d_in[3];
    const float* energy = (const float*)d_in[4];

    float* out  = (float*)d_out;                               // [B,T,H]
    float* attn = out + (size_t)BATCH*TSEQ*HDIM;               // [B,T,T]
    float* eout = attn + (size_t)BATCH*TSEQ*TSEQ;              // scalar

    cudaFuncSetAttribute(attn1_kernel, cudaFuncAttributeMaxDynamicSharedMemorySize, SMEM_DYN);

    zero_kernel<<<1, 1>>>();
    proj_kernel<<<dim3(NROWS/128, 3), 256>>>(x, Wq, Wk, Wv);
    attn1_kernel<<<dim3(TSEQ/128, BATCH), 256, SMEM_DYN>>>(attn, out);
    norm_kernel<<<NROWS, 256>>>(attn);
    fin_kernel<<<1, 1>>>(energy, eout);
}

// round 6
// speedup vs baseline: 2.0524x; 2.0503x over previous
#include <cuda_runtime.h>
#include <cuda_bf16.h>
#include <mma.h>
#include <math.h>
#include <stdint.h>

using namespace nvcuda;

#define BATCH 4
#define TSEQ  4096
#define DMODEL 1024
#define HDIM  64
#define NROWS (BATCH*TSEQ)

#define SCALE_Q 0.18033688011112042f   // log2(e)/8

// Scratch (device globals — no allocations allowed)
__device__ float g_q[NROWS*HDIM];
__device__ float g_k[NROWS*HDIM];
__device__ float g_v[NROWS*HDIM];
__device__ float g_rowsum[NROWS];
__device__ float g_ent;

__global__ void zero_kernel() { g_ent = 0.0f; }

__device__ __forceinline__ float ex2f_(float x){ float y; asm("ex2.approx.ftz.f32 %0, %1;" : "=f"(y) : "f"(x)); return y; }
__device__ __forceinline__ float lg2f_(float x){ float y; asm("lg2.approx.f32 %0, %1;" : "=f"(y) : "f"(x)); return y; }

__device__ __forceinline__ uint32_t pk2(float a, float b){
    __nv_bfloat162 t; t.x = __float2bfloat16(a); t.y = __float2bfloat16(b);
    return *reinterpret_cast<uint32_t*>(&t);
}
__device__ __forceinline__ uint32_t pk2f2(float2 v){
    __nv_bfloat162 t = __float22bfloat162_rn(v);
    return *reinterpret_cast<uint32_t*>(&t);
}
__device__ __forceinline__ float bflo(float f){
    return f - __bfloat162float(__float2bfloat16(f));
}

// raw mma m16n8k16 bf16 (A row-major, B col-major, f32 acc)
__device__ __forceinline__ void mma16816(float* c, const uint32_t* a, uint32_t b0, uint32_t b1){
    asm volatile("mma.sync.aligned.m16n8k16.row.col.f32.bf16.bf16.f32 "
        "{%0,%1,%2,%3}, {%4,%5,%6,%7}, {%8,%9}, {%0,%1,%2,%3};"
        : "+f"(c[0]), "+f"(c[1]), "+f"(c[2]), "+f"(c[3])
        : "r"(a[0]), "r"(a[1]), "r"(a[2]), "r"(a[3]), "r"(b0), "r"(b1));
}

// swizzled addressing: 128B rows (Q,K): row r, byte col cb (0..127)
__device__ __forceinline__ uint32_t swz(int r, int cb){
    return (uint32_t)(r*128 + (cb ^ ((r & 7) << 4)));
}
// VT rows: 256B (128 keys x bf16): swizzle within each 128B half
__device__ __forceinline__ uint32_t vswz(int h, int kb){
    return (uint32_t)(h*256 + (kb & 128) + ((kb & 127) ^ ((h & 7) << 4)));
}

typedef wmma::fragment<wmma::matrix_a, 16,16,16, __nv_bfloat16, wmma::row_major> FragA;
typedef wmma::fragment<wmma::matrix_b, 16,16,16, __nv_bfloat16, wmma::col_major> FragBc;
typedef wmma::fragment<wmma::accumulator, 16,16,16, float> FragC;

// ---------------------------------------------------------------------------
// K1: QKV projection via wmma bf16 hi/lo split (unchanged from R5, passing).
// ---------------------------------------------------------------------------
__global__ __launch_bounds__(256, 1) void proj_kernel(
    const float* __restrict__ x,
    const float* __restrict__ Wq,
    const float* __restrict__ Wk,
    const float* __restrict__ Wv)
{
    __shared__ __nv_bfloat16 xhi[128*64], xlo[128*64];
    __shared__ __nv_bfloat16 whi[64*64],  wlo[64*64];

    const float* W   = (blockIdx.y == 0) ? Wq : ((blockIdx.y == 1) ? Wk : Wv);
    float*       out = (blockIdx.y == 0) ? g_q : ((blockIdx.y == 1) ? g_k : g_v);

    const int row0 = blockIdx.x * 128;
    const int tid  = threadIdx.x;
    const int w    = tid >> 5;

    FragC acc[4];
    #pragma unroll
    for (int n = 0; n < 4; n++) wmma::fill_fragment(acc[n], 0.0f);

    for (int c0 = 0; c0 < DMODEL; c0 += 64) {
        __syncthreads();
        #pragma unroll
        for (int i = 0; i < 16; i++) {
            int p = i*256 + tid;
            int r = p >> 5, c2 = p & 31;
            float2 v = *(const float2*)&x[(size_t)(row0 + r)*DMODEL + c0 + 2*c2];
            ((uint32_t*)xhi)[r*32 + c2] = pk2f2(v);
            ((uint32_t*)xlo)[r*32 + c2] = pk2(bflo(v.x), bflo(v.y));
        }
        #pragma unroll
        for (int i = 0; i < 8; i++) {
            int p = i*256 + tid;
            int h = p >> 5, c2 = p & 31;
            float2 v = *(const float2*)&W[(size_t)h*DMODEL + c0 + 2*c2];
            ((uint32_t*)whi)[h*32 + c2] = pk2f2(v);
            ((uint32_t*)wlo)[h*32 + c2] = pk2(bflo(v.x), bflo(v.y));
        }
        __syncthreads();
        #pragma unroll
        for (int t = 0; t < 3; t++) {
            const __nv_bfloat16* A = (t == 2) ? xlo : xhi;
            const __nv_bfloat16* B = (t == 1) ? wlo : whi;
            #pragma unroll
            for (int kk = 0; kk < 4; kk++) {
                FragA af;
                wmma::load_matrix_sync(af, A + (16*w)*64 + kk*16, 64);
                #pragma unroll
                for (int n = 0; n < 4; n++) {
                    FragBc bf;
                    wmma::load_matrix_sync(bf, B + (n*16)*64 + kk*16, 64);
                    wmma::mma_sync(acc[n], af, bf, acc[n]);
                }
            }
        }
    }
    #pragma unroll
    for (int n = 0; n < 4; n++)
        wmma::store_matrix_sync(out + (size_t)(row0 + 16*w)*HDIM + n*16, acc[n], HDIM, wmma::mem_row_major);
}

// ---------------------------------------------------------------------------
// K2: fused attention, raw mma.sync (FA2-style register-resident P).
// grid (32, 4), 256 threads (8 warps x 16 q-rows). Chunk = 128 keys.
// ---------------------------------------------------------------------------
#define OQHI 0
#define OQLO 16384
#define OKHI 32768
#define OKLO 49152
#define OVTHI 65536
#define OVTLO 81920
#define SMEM_ATTN 98304

__global__ __launch_bounds__(256, 1) void attn2_kernel(float* __restrict__ attn,
                                                       float* __restrict__ out)
{
    extern __shared__ char sm[];
    __shared__ float s_ent[8];

    const int tid  = threadIdx.x;
    const int w    = tid >> 5;
    const int lane = tid & 31;
    const int g    = lane >> 2;      // group id (row within 8)
    const int tq   = lane & 3;       // thread-in-group
    const int b    = blockIdx.y;
    const int q0   = blockIdx.x * 128;
    const size_t rowg = (size_t)b*TSEQ + q0;  // CTA's first global row
    const int wr  = 16 * w;                    // warp's first row in tile

    // ---- Q convert: scale, hi/lo split, swizzled smem ----
    {
        const float* Qg = g_q + rowg*HDIM;
        #pragma unroll
        for (int i = 0; i < 16; i++) {
            int p = i*256 + tid;
            int r = p >> 5, c2 = p & 31;
            float2 v = *(const float2*)&Qg[(size_t)r*HDIM + 2*c2];
            v.x *= SCALE_Q; v.y *= SCALE_Q;
            *(uint32_t*)(sm + OQHI + swz(r, c2*4)) = pk2f2(v);
            *(uint32_t*)(sm + OQLO + swz(r, c2*4)) = pk2(bflo(v.x), bflo(v.y));
        }
    }
    __syncthreads();

    // ---- Q fragments, held in registers for the whole kernel ----
    uint32_t qh[4][4], ql[4][4];
    #pragma unroll
    for (int ks = 0; ks < 4; ks++) {
        int kb = ks*32 + tq*4;
        qh[ks][0] = *(const uint32_t*)(sm + OQHI + swz(wr+g,   kb));
        qh[ks][1] = *(const uint32_t*)(sm + OQHI + swz(wr+g+8, kb));
        qh[ks][2] = *(const uint32_t*)(sm + OQHI + swz(wr+g,   kb+16));
        qh[ks][3] = *(const uint32_t*)(sm + OQHI + swz(wr+g+8, kb+16));
        ql[ks][0] = *(const uint32_t*)(sm + OQLO + swz(wr+g,   kb));
        ql[ks][1] = *(const uint32_t*)(sm + OQLO + swz(wr+g+8, kb));
        ql[ks][2] = *(const uint32_t*)(sm + OQLO + swz(wr+g,   kb+16));
        ql[ks][3] = *(const uint32_t*)(sm + OQLO + swz(wr+g+8, kb+16));
    }

    float oacc[8][4];
    #pragma unroll
    for (int n = 0; n < 8; n++)
        #pragma unroll
        for (int j = 0; j < 4; j++) oacc[n][j] = 0.0f;

    float Zr0 = 0.f, Zr1 = 0.f, Er0 = 0.f, Er1 = 0.f;

    for (int c = 0; c < TSEQ/128; c++) {
        const float* Kg = g_k + (rowg - q0 + (size_t)c*128)*HDIM + (size_t)0; // b*T + c*128
        const float* Vg = g_v + ((size_t)b*TSEQ + c*128)*HDIM;
        __syncthreads();   // prior chunk's K/VT reads complete
        // K convert
        #pragma unroll
        for (int i = 0; i < 16; i++) {
            int p = i*256 + tid;
            int r = p >> 5, c2 = p & 31;
            float2 v = *(const float2*)&Kg[(size_t)r*HDIM + 2*c2];
            *(uint32_t*)(sm + OKHI + swz(r, c2*4)) = pk2f2(v);
            *(uint32_t*)(sm + OKLO + swz(r, c2*4)) = pk2(bflo(v.x), bflo(v.y));
        }
        // V convert, transposed to [h][k]
        {
            int h = tid & 63, kp0 = tid >> 6;
            #pragma unroll
            for (int i = 0; i < 16; i++) {
                int pi = kp0 + 4*i;        // b32 pair index 0..63
                int k = 2*pi;
                float v0 = Vg[(size_t)k*HDIM + h];
                float v1 = Vg[(size_t)(k+1)*HDIM + h];
                *(uint32_t*)(sm + OVTHI + vswz(h, 4*pi)) = pk2(v0, v1);
                *(uint32_t*)(sm + OVTLO + vswz(h, 4*pi)) = pk2(bflo(v0), bflo(v1));
            }
        }
        __syncthreads();

        // ---- S = Q K^T : 16 rows x 128 keys per warp ----
        float sacc[16][4];
        #pragma unroll
        for (int n = 0; n < 16; n++)
            #pragma unroll
            for (int j = 0; j < 4; j++) sacc[n][j] = 0.0f;

        #pragma unroll
        for (int nt = 0; nt < 16; nt++) {
            #pragma unroll
            for (int ks = 0; ks < 4; ks++) {
                int kb = ks*32 + tq*4;
                int kr = nt*8 + g;
                uint32_t bh0 = *(const uint32_t*)(sm + OKHI + swz(kr, kb));
                uint32_t bh1 = *(const uint32_t*)(sm + OKHI + swz(kr, kb+16));
                uint32_t bl0 = *(const uint32_t*)(sm + OKLO + swz(kr, kb));
                uint32_t bl1 = *(const uint32_t*)(sm + OKLO + swz(kr, kb+16));
                mma16816(sacc[nt], qh[ks], bh0, bh1);   // hi*hi
                mma16816(sacc[nt], qh[ks], bl0, bl1);   // hi*lo
                mma16816(sacc[nt], ql[ks], bh0, bh1);   // lo*hi
            }
        }

        // ---- exp, entropy/rowsum partials, attn store, P frags in regs ----
        uint32_t ph[8][4], pl[8][4];
        float* arow0 = attn + (rowg + wr + g)*TSEQ + c*128 + 2*tq;
        float* arow1 = arow0 + (size_t)8*TSEQ;
        #pragma unroll
        for (int ks = 0; ks < 8; ks++) {
            #pragma unroll
            for (int h2 = 0; h2 < 2; h2++) {
                int nt = 2*ks + h2;
                float s0 = sacc[nt][0], s1 = sacc[nt][1], s2 = sacc[nt][2], s3 = sacc[nt][3];
                float e0 = ex2f_(s0), e1 = ex2f_(s1), e2 = ex2f_(s2), e3 = ex2f_(s3);
                Zr0 += e0 + e1;  Er0 += e0*s0 + e1*s1;
                Zr1 += e2 + e3;  Er1 += e2*s2 + e3*s3;
                *(float2*)(arow0 + nt*8) = make_float2(e0, e1);
                *(float2*)(arow1 + nt*8) = make_float2(e2, e3);
                if (h2 == 0) {
                    ph[ks][0] = pk2(e0, e1);           ph[ks][1] = pk2(e2, e3);
                    pl[ks][0] = pk2(bflo(e0), bflo(e1)); pl[ks][1] = pk2(bflo(e2), bflo(e3));
                } else {
                    ph[ks][2] = pk2(e0, e1);           ph[ks][3] = pk2(e2, e3);
                    pl[ks][2] = pk2(bflo(e0), bflo(e1)); pl[ks][3] = pk2(bflo(e2), bflo(e3));
                }
            }
        }

        // ---- O += P V ----
        #pragma unroll
        for (int nt = 0; nt < 8; nt++) {
            #pragma unroll
            for (int ks = 0; ks < 8; ks++) {
                int kb = ks*32 + tq*4;
                int h  = nt*8 + g;
                uint32_t vh0 = *(const uint32_t*)(sm + OVTHI + vswz(h, kb));
                uint32_t vh1 = *(const uint32_t*)(sm + OVTHI + vswz(h, kb+16));
                uint32_t vl0 = *(const uint32_t*)(sm + OVTLO + vswz(h, kb));
                uint32_t vl1 = *(const uint32_t*)(sm + OVTLO + vswz(h, kb+16));
                mma16816(oacc[nt], ph[ks], vh0, vh1);   // hi*hi
                mma16816(oacc[nt], ph[ks], vl0, vl1);   // hi*lo
                mma16816(oacc[nt], pl[ks], vh0, vh1);   // lo*hi
            }
        }
    }

    // ---- reductions over the 4 lanes of each group ----
    #pragma unroll
    for (int off = 1; off <= 2; off <<= 1) {
        Zr0 += __shfl_xor_sync(0xffffffffu, Zr0, off);
        Zr1 += __shfl_xor_sync(0xffffffffu, Zr1, off);
        Er0 += __shfl_xor_sync(0xffffffffu, Er0, off);
        Er1 += __shfl_xor_sync(0xffffffffu, Er1, off);
    }
    const float inv0 = __fdividef(1.0f, Zr0);
    const float inv1 = __fdividef(1.0f, Zr1);

    // O write (scaled by 1/Z)
    float* orow0 = out + (rowg + wr + g)*HDIM + 2*tq;
    float* orow1 = orow0 + (size_t)8*HDIM;
    #pragma unroll
    for (int nt = 0; nt < 8; nt++) {
        *(float2*)(orow0 + nt*8) = make_float2(oacc[nt][0]*inv0, oacc[nt][1]*inv0);
        *(float2*)(orow1 + nt*8) = make_float2(oacc[nt][2]*inv1, oacc[nt][3]*inv1);
    }
    if (tq == 0) {
        g_rowsum[rowg + wr + g]     = Zr0;
        g_rowsum[rowg + wr + g + 8] = Zr1;
    }

    // entropy partial: per row H/ln2 = lg2(Z) - E/Z
    float hh = (tq == 0) ? (lg2f_(Zr0) - Er0*inv0) + (lg2f_(Zr1) - Er1*inv1) : 0.0f;
    #pragma unroll
    for (int off = 16; off > 0; off >>= 1) hh += __shfl_xor_sync(0xffffffffu, hh, off);
    if (lane == 0) s_ent[w] = hh;
    __syncthreads();
    if (tid == 0) {
        float t = 0.0f;
        #pragma unroll
        for (int i = 0; i < 8; i++) t += s_ent[i];
        atomicAdd(&g_ent, t);
    }
}

// ---------------------------------------------------------------------------
// K3: normalize attn rows in place:  P = E / Z
// ---------------------------------------------------------------------------
__global__ __launch_bounds__(256) void norm_kernel(float* __restrict__ attn)
{
    const size_t row = blockIdx.x;
    const float inv = 1.0f / g_rowsum[row];
    float4* p = (float4*)(attn + row*TSEQ);
    const int tid = threadIdx.x;
    #pragma unroll
    for (int j = 0; j < 4; j++) {
        int idx = tid + j*256;
        float4 v = p[idx];
        v.x *= inv; v.y *= inv; v.z *= inv; v.w *= inv;
        p[idx] = v;
    }
}

// ---------------------------------------------------------------------------
// K4: finalize energy EMA.  H_mean = ln2 * g_ent / NROWS
// ---------------------------------------------------------------------------
__global__ void fin_kernel(const float* __restrict__ energy, float* __restrict__ eout)
{
    float ent_mean = 0.6931471805599453f * g_ent / (float)NROWS;
    *eout = 0.9f * energy[0] + 0.1f * ent_mean;
}

// ---------------------------------------------------------------------------
extern "C" void kernel_launch(void* const* d_in, const int* in_sizes, int n_in,
                              void* d_out, int out_size)
{
    const float* x      = (const float*)d_in[0];
    const float* Wq     = (const float*)d_in[1];
    const float* Wk     = (const float*)d_in[2];
    const float* Wv     = (const float*)d_in[3];
    const float* energy = (const float*)d_in[4];

    float* out  = (float*)d_out;                               // [B,T,H]
    float* attn = out + (size_t)BATCH*TSEQ*HDIM;               // [B,T,T]
    float* eout = attn + (size_t)BATCH*TSEQ*TSEQ;              // scalar

    cudaFuncSetAttribute(attn2_kernel, cudaFuncAttributeMaxDynamicSharedMemorySize, SMEM_ATTN);

    zero_kernel<<<1, 1>>>();
    proj_kernel<<<dim3(NROWS/128, 3), 256>>>(x, Wq, Wk, Wv);
    attn2_kernel<<<dim3(TSEQ/128, BATCH), 256, SMEM_ATTN>>>(attn, out);
    norm_kernel<<<NROWS, 256>>>(attn);
    fin_kernel<<<1, 1>>>(energy, eout);
}

// round 7
// speedup vs baseline: 2.2872x; 1.1144x over previous
#include <cuda_runtime.h>
#include <cuda_bf16.h>
#include <mma.h>
#include <math.h>
#include <stdint.h>

using namespace nvcuda;

#define BATCH 4
#define TSEQ  4096
#define DMODEL 1024
#define HDIM  64
#define NROWS (BATCH*TSEQ)
#define NTILE (NROWS/128)          // 128 tiles of 128 rows

#define SCALE_Q 0.18033688011112042f   // log2(e)/8

// Scratch: preformatted bf16 hi/lo tiles (swizzled smem images)
// Q/K tiles: 128 rows x 128B (swz) = 16KB per tile
// VT tiles:  64 rows x 256B (vswz) = 16KB per tile (one per 128-key chunk)
__device__ __align__(16) __nv_bfloat16 g_qhi[NROWS*HDIM];
__device__ __align__(16) __nv_bfloat16 g_qlo[NROWS*HDIM];
__device__ __align__(16) __nv_bfloat16 g_khi[NROWS*HDIM];
__device__ __align__(16) __nv_bfloat16 g_klo[NROWS*HDIM];
__device__ __align__(16) __nv_bfloat16 g_vthi[NROWS*HDIM];
__device__ __align__(16) __nv_bfloat16 g_vtlo[NROWS*HDIM];
__device__ float g_rowsum[NROWS];
__device__ float g_ent;

__device__ __forceinline__ float ex2f_(float x){ float y; asm("ex2.approx.ftz.f32 %0, %1;" : "=f"(y) : "f"(x)); return y; }
__device__ __forceinline__ float lg2f_(float x){ float y; asm("lg2.approx.f32 %0, %1;" : "=f"(y) : "f"(x)); return y; }

__device__ __forceinline__ uint32_t pk2(float a, float b){
    __nv_bfloat162 t; t.x = __float2bfloat16(a); t.y = __float2bfloat16(b);
    return *reinterpret_cast<uint32_t*>(&t);
}
__device__ __forceinline__ float bflo(float f){
    return f - __bfloat162float(__float2bfloat16(f));
}
__device__ __forceinline__ uint32_t smem_u32(const void* p){
    uint32_t a;
    asm("{ .reg .u64 t; cvta.to.shared.u64 t, %1; cvt.u32.u64 %0, t; }" : "=r"(a) : "l"(p));
    return a;
}
__device__ __forceinline__ void cpa16(uint32_t s, const void* g){
    asm volatile("cp.async.cg.shared.global [%0], [%1], 16;" :: "r"(s), "l"(g));
}
#define CPA_COMMIT() asm volatile("cp.async.commit_group;" ::: "memory")
#define CPA_WAIT0()  asm volatile("cp.async.wait_group 0;" ::: "memory")
#define CPA_WAIT1()  asm volatile("cp.async.wait_group 1;" ::: "memory")

// raw mma m16n8k16 bf16 (A row-major, B col-major, f32 acc)
__device__ __forceinline__ void mma16816(float* c, const uint32_t* a, uint32_t b0, uint32_t b1){
    asm volatile("mma.sync.aligned.m16n8k16.row.col.f32.bf16.bf16.f32 "
        "{%0,%1,%2,%3}, {%4,%5,%6,%7}, {%8,%9}, {%0,%1,%2,%3};"
        : "+f"(c[0]), "+f"(c[1]), "+f"(c[2]), "+f"(c[3])
        : "r"(a[0]), "r"(a[1]), "r"(a[2]), "r"(a[3]), "r"(b0), "r"(b1));
}

// swizzled addressing: Q/K tiles: 128B rows, row r (0..127), byte col cb (0..127)
__device__ __forceinline__ uint32_t swz(int r, int cb){
    return (uint32_t)(r*128 + (cb ^ ((r & 7) << 4)));
}
// VT tiles: 256B rows (128 keys bf16), swizzle within each 128B half
__device__ __forceinline__ uint32_t vswz(int h, int kb){
    return (uint32_t)(h*256 + (kb & 128) + ((kb & 127) ^ ((h & 7) << 4)));
}

typedef wmma::fragment<wmma::matrix_a, 16,16,16, __nv_bfloat16, wmma::row_major> FragA;
typedef wmma::fragment<wmma::matrix_b, 16,16,16, __nv_bfloat16, wmma::col_major> FragBc;
typedef wmma::fragment<wmma::accumulator, 16,16,16, float> FragC;

// ---------------------------------------------------------------------------
// K1: fused QKV projection. One CTA = 128 rows, computes Q, K, V together
// (x read ONCE), writes bf16 hi/lo swizzled tile images consumed by attn2.
// ---------------------------------------------------------------------------
#define PX_XHI 0
#define PX_XLO 16384
#define PX_WHI 32768          // 3 x 8192B (q,k,v)
#define PX_WLO 57344          // 3 x 8192B
#define PX_STG 81920          // 32KB fp32 staging
#define SMEM_PROJ 114688

__global__ __launch_bounds__(256, 1) void proj_kernel(
    const float* __restrict__ x,
    const float* __restrict__ Wq,
    const float* __restrict__ Wk,
    const float* __restrict__ Wv)
{
    extern __shared__ char sm[];
    __nv_bfloat16* xhi = (__nv_bfloat16*)(sm + PX_XHI);
    __nv_bfloat16* xlo = (__nv_bfloat16*)(sm + PX_XLO);
    float* stg = (float*)(sm + PX_STG);

    const float* Wm[3] = {Wq, Wk, Wv};
    const int tile = blockIdx.x;
    const int row0 = tile * 128;
    const int tid  = threadIdx.x;
    const int w    = tid >> 5;

    if (tile == 0 && tid == 0) g_ent = 0.0f;

    FragC acc[3][4];
    #pragma unroll
    for (int m = 0; m < 3; m++)
        #pragma unroll
        for (int n = 0; n < 4; n++) wmma::fill_fragment(acc[m][n], 0.0f);

    for (int c0 = 0; c0 < DMODEL; c0 += 64) {
        __syncthreads();
        #pragma unroll
        for (int i = 0; i < 16; i++) {            // x chunk 128x64 -> hi/lo
            int p = i*256 + tid;
            int r = p >> 5, c2 = p & 31;
            float2 v = *(const float2*)&x[(size_t)(row0 + r)*DMODEL + c0 + 2*c2];
            ((uint32_t*)xhi)[r*32 + c2] = pk2(v.x, v.y);
            ((uint32_t*)xlo)[r*32 + c2] = pk2(bflo(v.x), bflo(v.y));
        }
        #pragma unroll
        for (int m = 0; m < 3; m++) {             // W chunks 64x64 each
            __nv_bfloat16* whi = (__nv_bfloat16*)(sm + PX_WHI + m*8192);
            __nv_bfloat16* wlo = (__nv_bfloat16*)(sm + PX_WLO + m*8192);
            #pragma unroll
            for (int i = 0; i < 8; i++) {
                int p = i*256 + tid;
                int h = p >> 5, c2 = p & 31;
                float2 v = *(const float2*)&Wm[m][(size_t)h*DMODEL + c0 + 2*c2];
                ((uint32_t*)whi)[h*32 + c2] = pk2(v.x, v.y);
                ((uint32_t*)wlo)[h*32 + c2] = pk2(bflo(v.x), bflo(v.y));
            }
        }
        __syncthreads();
        #pragma unroll
        for (int t = 0; t < 3; t++) {
            const __nv_bfloat16* A = (t == 2) ? xlo : xhi;
            #pragma unroll
            for (int kk = 0; kk < 4; kk++) {
                FragA af;
                wmma::load_matrix_sync(af, A + (16*w)*64 + kk*16, 64);
                #pragma unroll
                for (int m = 0; m < 3; m++) {
                    const __nv_bfloat16* B = (__nv_bfloat16*)(sm + ((t == 1) ? PX_WLO : PX_WHI) + m*8192);
                    #pragma unroll
                    for (int n = 0; n < 4; n++) {
                        FragBc bf;
                        wmma::load_matrix_sync(bf, B + (n*16)*64 + kk*16, 64);
                        wmma::mma_sync(acc[m][n], af, bf, acc[m][n]);
                    }
                }
            }
        }
    }

    // ---- stage each matrix through smem fp32, split hi/lo, write tiles ----
    #pragma unroll
    for (int m = 0; m < 3; m++) {
        __syncthreads();
        #pragma unroll
        for (int n = 0; n < 4; n++)
            wmma::store_matrix_sync(stg + (16*w)*64 + n*16, acc[m][n], 64, wmma::mem_row_major);
        __syncthreads();
        if (m < 2) {                               // Q (scaled) or K
            const float sc = (m == 0) ? SCALE_Q : 1.0f;
            char* dhi = (char*)((m == 0) ? g_qhi : g_khi) + (size_t)tile*16384;
            char* dlo = (char*)((m == 0) ? g_qlo : g_klo) + (size_t)tile*16384;
            #pragma unroll
            for (int i = 0; i < 16; i++) {
                int p = i*256 + tid;
                int r = p >> 5, c2 = p & 31;
                float f0 = stg[r*64 + 2*c2] * sc;
                float f1 = stg[r*64 + 2*c2 + 1] * sc;
                uint32_t off = swz(r, c2*4);
                *(uint32_t*)(dhi + off) = pk2(f0, f1);
                *(uint32_t*)(dlo + off) = pk2(bflo(f0), bflo(f1));
            }
        } else {                                   // V transposed
            char* dhi = (char*)g_vthi + (size_t)tile*16384;
            char* dlo = (char*)g_vtlo + (size_t)tile*16384;
            int h = tid & 63, kp0 = tid >> 6;
            #pragma unroll
            for (int i = 0; i < 16; i++) {
                int pi = kp0 + 4*i;                // b32 pair index 0..63
                int k = 2*pi;
                float v0 = stg[k*64 + h];
                float v1 = stg[(k+1)*64 + h];
                uint32_t off = vswz(h, 4*pi);
                *(uint32_t*)(dhi + off) = pk2(v0, v1);
                *(uint32_t*)(dlo + off) = pk2(bflo(v0), bflo(v1));
            }
        }
    }
}

// ---------------------------------------------------------------------------
// K2: fused attention: cp.async double-buffered preformatted tiles + mma.sync
// grid (32, 4), 256 threads (8 warps x 16 q-rows). Chunk = 128 keys.
// ---------------------------------------------------------------------------
#define OQHI 0
#define OQLO 16384
#define OBUF 32768            // 2 x 64KB: [KHI|KLO|VTHI|VTLO] each 16KB
#define SMEM_ATTN 163840

__global__ __launch_bounds__(256, 1) void attn2_kernel(float* __restrict__ attn,
                                                       float* __restrict__ out)
{
    extern __shared__ char sm[];
    __shared__ float s_ent[8];

    const int tid  = threadIdx.x;
    const int w    = tid >> 5;
    const int lane = tid & 31;
    const int g    = lane >> 2;
    const int tq   = lane & 3;
    const int b    = blockIdx.y;
    const int q0   = blockIdx.x * 128;
    const size_t rowg = (size_t)b*TSEQ + q0;
    const int wr  = 16 * w;
    const uint32_t smb = smem_u32(sm);

    const int tile_q  = b*(TSEQ/128) + blockIdx.x;
    const int tile_k0 = b*(TSEQ/128);

    // ---- async copy Q tile (hi+lo), prefetch chunk 0 ----
    {
        const char* gq_hi = (const char*)g_qhi + (size_t)tile_q*16384;
        const char* gq_lo = (const char*)g_qlo + (size_t)tile_q*16384;
        #pragma unroll
        for (int i = 0; i < 4; i++) {
            uint32_t off = (uint32_t)(i*4096 + tid*16);
            cpa16(smb + OQHI + off, gq_hi + off);
            cpa16(smb + OQLO + off, gq_lo + off);
        }
        CPA_COMMIT();
        const char* gk_hi = (const char*)g_khi  + (size_t)tile_k0*16384;
        const char* gk_lo = (const char*)g_klo  + (size_t)tile_k0*16384;
        const char* gv_hi = (const char*)g_vthi + (size_t)tile_k0*16384;
        const char* gv_lo = (const char*)g_vtlo + (size_t)tile_k0*16384;
        #pragma unroll
        for (int i = 0; i < 4; i++) {
            uint32_t off = (uint32_t)(i*4096 + tid*16);
            cpa16(smb + OBUF + off,         gk_hi + off);
            cpa16(smb + OBUF + 16384 + off, gk_lo + off);
            cpa16(smb + OBUF + 32768 + off, gv_hi + off);
            cpa16(smb + OBUF + 49152 + off, gv_lo + off);
        }
        CPA_COMMIT();
        CPA_WAIT0();
    }
    __syncthreads();

    // ---- Q fragments, held in registers ----
    uint32_t qh[4][4], ql[4][4];
    #pragma unroll
    for (int ks = 0; ks < 4; ks++) {
        int kb = ks*32 + tq*4;
        qh[ks][0] = *(const uint32_t*)(sm + OQHI + swz(wr+g,   kb));
        qh[ks][1] = *(const uint32_t*)(sm + OQHI + swz(wr+g+8, kb));
        qh[ks][2] = *(const uint32_t*)(sm + OQHI + swz(wr+g,   kb+16));
        qh[ks][3] = *(const uint32_t*)(sm + OQHI + swz(wr+g+8, kb+16));
        ql[ks][0] = *(const uint32_t*)(sm + OQLO + swz(wr+g,   kb));
        ql[ks][1] = *(const uint32_t*)(sm + OQLO + swz(wr+g+8, kb));
        ql[ks][2] = *(const uint32_t*)(sm + OQLO + swz(wr+g,   kb+16));
        ql[ks][3] = *(const uint32_t*)(sm + OQLO + swz(wr+g+8, kb+16));
    }

    float oacc[8][4];
    #pragma unroll
    for (int n = 0; n < 8; n++)
        #pragma unroll
        for (int j = 0; j < 4; j++) oacc[n][j] = 0.0f;

    float Zr0 = 0.f, Zr1 = 0.f, Er0 = 0.f, Er1 = 0.f;

    for (int c = 0; c < TSEQ/128; c++) {
        __syncthreads();                        // all warps done with buf[(c+1)&1]
        if (c < TSEQ/128 - 1) {
            const size_t tn = (size_t)(tile_k0 + c + 1)*16384;
            const uint32_t dst = smb + OBUF + (uint32_t)(((c+1)&1)*65536);
            const char* gk_hi = (const char*)g_khi  + tn;
            const char* gk_lo = (const char*)g_klo  + tn;
            const char* gv_hi = (const char*)g_vthi + tn;
            const char* gv_lo = (const char*)g_vtlo + tn;
            #pragma unroll
            for (int i = 0; i < 4; i++) {
                uint32_t off = (uint32_t)(i*4096 + tid*16);
                cpa16(dst + off,         gk_hi + off);
                cpa16(dst + 16384 + off, gk_lo + off);
                cpa16(dst + 32768 + off, gv_hi + off);
                cpa16(dst + 49152 + off, gv_lo + off);
            }
            CPA_COMMIT();
            CPA_WAIT1();                        // chunk c complete
        } else {
            CPA_WAIT0();
        }
        __syncthreads();

        const char* bk = sm + OBUF + (c&1)*65536;          // KHI
        const char* bklo = bk + 16384;
        const char* bv = bk + 32768;                        // VTHI
        const char* bvlo = bk + 49152;

        // ---- S = Q K^T : 16 rows x 128 keys per warp ----
        float sacc[16][4];
        #pragma unroll
        for (int n = 0; n < 16; n++)
            #pragma unroll
            for (int j = 0; j < 4; j++) sacc[n][j] = 0.0f;

        #pragma unroll
        for (int nt = 0; nt < 16; nt++) {
            #pragma unroll
            for (int ks = 0; ks < 4; ks++) {
                int kb = ks*32 + tq*4;
                int kr = nt*8 + g;
                uint32_t bh0 = *(const uint32_t*)(bk   + swz(kr, kb));
                uint32_t bh1 = *(const uint32_t*)(bk   + swz(kr, kb+16));
                uint32_t bl0 = *(const uint32_t*)(bklo + swz(kr, kb));
                uint32_t bl1 = *(const uint32_t*)(bklo + swz(kr, kb+16));
                mma16816(sacc[nt], qh[ks], bh0, bh1);
                mma16816(sacc[nt], qh[ks], bl0, bl1);
                mma16816(sacc[nt], ql[ks], bh0, bh1);
            }
        }

        // ---- exp, partials, attn store, P frags in regs ----
        uint32_t ph[8][4], pl[8][4];
        float* arow0 = attn + (rowg + wr + g)*TSEQ + c*128 + 2*tq;
        float* arow1 = arow0 + (size_t)8*TSEQ;
        #pragma unroll
        for (int ks = 0; ks < 8; ks++) {
            #pragma unroll
            for (int h2 = 0; h2 < 2; h2++) {
                int nt = 2*ks + h2;
                float s0 = sacc[nt][0], s1 = sacc[nt][1], s2 = sacc[nt][2], s3 = sacc[nt][3];
                float e0 = ex2f_(s0), e1 = ex2f_(s1), e2 = ex2f_(s2), e3 = ex2f_(s3);
                Zr0 += e0 + e1;  Er0 += e0*s0 + e1*s1;
                Zr1 += e2 + e3;  Er1 += e2*s2 + e3*s3;
                *(float2*)(arow0 + nt*8) = make_float2(e0, e1);
                *(float2*)(arow1 + nt*8) = make_float2(e2, e3);
                if (h2 == 0) {
                    ph[ks][0] = pk2(e0, e1);             ph[ks][1] = pk2(e2, e3);
                    pl[ks][0] = pk2(bflo(e0), bflo(e1)); pl[ks][1] = pk2(bflo(e2), bflo(e3));
                } else {
                    ph[ks][2] = pk2(e0, e1);             ph[ks][3] = pk2(e2, e3);
                    pl[ks][2] = pk2(bflo(e0), bflo(e1)); pl[ks][3] = pk2(bflo(e2), bflo(e3));
                }
            }
        }

        // ---- O += P V ----
        #pragma unroll
        for (int nt = 0; nt < 8; nt++) {
            #pragma unroll
            for (int ks = 0; ks < 8; ks++) {
                int kb = ks*32 + tq*4;
                int h  = nt*8 + g;
                uint32_t vh0 = *(const uint32_t*)(bv   + vswz(h, kb));
                uint32_t vh1 = *(const uint32_t*)(bv   + vswz(h, kb+16));
                uint32_t vl0 = *(const uint32_t*)(bvlo + vswz(h, kb));
                uint32_t vl1 = *(const uint32_t*)(bvlo + vswz(h, kb+16));
                mma16816(oacc[nt], ph[ks], vh0, vh1);
                mma16816(oacc[nt], ph[ks], vl0, vl1);
                mma16816(oacc[nt], pl[ks], vh0, vh1);
            }
        }
    }

    // ---- reductions over the 4 lanes of each group ----
    #pragma unroll
    for (int off = 1; off <= 2; off <<= 1) {
        Zr0 += __shfl_xor_sync(0xffffffffu, Zr0, off);
        Zr1 += __shfl_xor_sync(0xffffffffu, Zr1, off);
        Er0 += __shfl_xor_sync(0xffffffffu, Er0, off);
        Er1 += __shfl_xor_sync(0xffffffffu, Er1, off);
    }
    const float inv0 = __fdividef(1.0f, Zr0);
    const float inv1 = __fdividef(1.0f, Zr1);

    float* orow0 = out + (rowg + wr + g)*HDIM + 2*tq;
    float* orow1 = orow0 + (size_t)8*HDIM;
    #pragma unroll
    for (int nt = 0; nt < 8; nt++) {
        *(float2*)(orow0 + nt*8) = make_float2(oacc[nt][0]*inv0, oacc[nt][1]*inv0);
        *(float2*)(orow1 + nt*8) = make_float2(oacc[nt][2]*inv1, oacc[nt][3]*inv1);
    }
    if (tq == 0) {
        g_rowsum[rowg + wr + g]     = Zr0;
        g_rowsum[rowg + wr + g + 8] = Zr1;
    }

    float hh = (tq == 0) ? (lg2f_(Zr0) - Er0*inv0) + (lg2f_(Zr1) - Er1*inv1) : 0.0f;
    #pragma unroll
    for (int off = 16; off > 0; off >>= 1) hh += __shfl_xor_sync(0xffffffffu, hh, off);
    if (lane == 0) s_ent[w] = hh;
    __syncthreads();
    if (tid == 0) {
        float t = 0.0f;
        #pragma unroll
        for (int i = 0; i < 8; i++) t += s_ent[i];
        atomicAdd(&g_ent, t);
    }
}

// ---------------------------------------------------------------------------
// K3: normalize attn rows in place:  P = E / Z
// ---------------------------------------------------------------------------
__global__ __launch_bounds__(256) void norm_kernel(float* __restrict__ attn)
{
    const size_t row = blockIdx.x;
    const float inv = 1.0f / g_rowsum[row];
    float4* p = (float4*)(attn + row*TSEQ);
    const int tid = threadIdx.x;
    #pragma unroll
    for (int j = 0; j < 4; j++) {
        int idx = tid + j*256;
        float4 v = p[idx];
        v.x *= inv; v.y *= inv; v.z *= inv; v.w *= inv;
        p[idx] = v;
    }
}

// ---------------------------------------------------------------------------
// K4: finalize energy EMA.  H_mean = ln2 * g_ent / NROWS
// ---------------------------------------------------------------------------
__global__ void fin_kernel(const float* __restrict__ energy, float* __restrict__ eout)
{
    float ent_mean = 0.6931471805599453f * g_ent / (float)NROWS;
    *eout = 0.9f * energy[0] + 0.1f * ent_mean;
}

// ---------------------------------------------------------------------------
extern "C" void kernel_launch(void* const* d_in, const int* in_sizes, int n_in,
                              void* d_out, int out_size)
{
    const float* x      = (const float*)d_in[0];
    const float* Wq     = (const float*)d_in[1];
    const float* Wk     = (const float*)d_in[2];
    const float* Wv     = (const float*)d_in[3];
    const float* energy = (const float*)d_in[4];

    float* out  = (float*)d_out;                               // [B,T,H]
    float* attn = out + (size_t)BATCH*TSEQ*HDIM;               // [B,T,T]
    float* eout = attn + (size_t)BATCH*TSEQ*TSEQ;              // scalar

    cudaFuncSetAttribute(proj_kernel,  cudaFuncAttributeMaxDynamicSharedMemorySize, SMEM_PROJ);
    cudaFuncSetAttribute(attn2_kernel, cudaFuncAttributeMaxDynamicSharedMemorySize, SMEM_ATTN);

    proj_kernel<<<NTILE, 256, SMEM_PROJ>>>(x, Wq, Wk, Wv);
    attn2_kernel<<<dim3(TSEQ/128, BATCH), 256, SMEM_ATTN>>>(attn, out);
    norm_kernel<<<NROWS, 256>>>(attn);
    fin_kernel<<<1, 1>>>(energy, eout);
}

// round 8
// speedup vs baseline: 2.4907x; 1.0890x over previous
#include <cuda_runtime.h>
#include <cuda_bf16.h>
#include <mma.h>
#include <math.h>
#include <stdint.h>

using namespace nvcuda;

#define BATCH 4
#define TSEQ  4096
#define DMODEL 1024
#define HDIM  64
#define NROWS (BATCH*TSEQ)
#define NTILE (NROWS/128)

#define SCALE_Q 0.18033688011112042f   // log2(e)/8

// Scratch: preformatted bf16 hi/lo tiles (swizzled smem images)
__device__ __align__(16) __nv_bfloat16 g_qhi[NROWS*HDIM];
__device__ __align__(16) __nv_bfloat16 g_qlo[NROWS*HDIM];
__device__ __align__(16) __nv_bfloat16 g_khi[NROWS*HDIM];
__device__ __align__(16) __nv_bfloat16 g_klo[NROWS*HDIM];
__device__ __align__(16) __nv_bfloat16 g_vthi[NROWS*HDIM];
__device__ __align__(16) __nv_bfloat16 g_vtlo[NROWS*HDIM];
__device__ float g_ent;

__device__ __forceinline__ float ex2f_(float x){ float y; asm("ex2.approx.ftz.f32 %0, %1;" : "=f"(y) : "f"(x)); return y; }
__device__ __forceinline__ float lg2f_(float x){ float y; asm("lg2.approx.f32 %0, %1;" : "=f"(y) : "f"(x)); return y; }

// pack (a -> low half, b -> high half) as bf16x2 in one cvt
__device__ __forceinline__ uint32_t pk2(float a, float b){
    uint32_t r;
    asm("cvt.rn.bf16x2.f32 %0, %1, %2;" : "=r"(r) : "f"(b), "f"(a));
    return r;
}
__device__ __forceinline__ float bflo(float f){
    return f - __bfloat162float(__float2bfloat16(f));
}
// residuals of a packed pair: lo parts of (a,b) given u = pk2(a,b)
__device__ __forceinline__ uint32_t pk2lo(float a, float b, uint32_t u){
    float hi_a = __uint_as_float(u << 16);
    float hi_b = __uint_as_float(u & 0xffff0000u);
    return pk2(a - hi_a, b - hi_b);
}
__device__ __forceinline__ uint32_t smem_u32(const void* p){
    uint32_t a;
    asm("{ .reg .u64 t; cvta.to.shared.u64 t, %1; cvt.u32.u64 %0, t; }" : "=r"(a) : "l"(p));
    return a;
}
__device__ __forceinline__ void cpa16(uint32_t s, const void* g){
    asm volatile("cp.async.cg.shared.global [%0], [%1], 16;" :: "r"(s), "l"(g));
}
#define CPA_COMMIT() asm volatile("cp.async.commit_group;" ::: "memory")
#define CPA_WAIT0()  asm volatile("cp.async.wait_group 0;" ::: "memory")
#define CPA_WAIT1()  asm volatile("cp.async.wait_group 1;" ::: "memory")

__device__ __forceinline__ void mma16816(float* c, const uint32_t* a, uint32_t b0, uint32_t b1){
    asm volatile("mma.sync.aligned.m16n8k16.row.col.f32.bf16.bf16.f32 "
        "{%0,%1,%2,%3}, {%4,%5,%6,%7}, {%8,%9}, {%0,%1,%2,%3};"
        : "+f"(c[0]), "+f"(c[1]), "+f"(c[2]), "+f"(c[3])
        : "r"(a[0]), "r"(a[1]), "r"(a[2]), "r"(a[3]), "r"(b0), "r"(b1));
}

// Q/K tiles: 128B rows, row r (0..127), byte col cb (0..127)
__device__ __forceinline__ uint32_t swz(int r, int cb){
    return (uint32_t)(r*128 + (cb ^ ((r & 7) << 4)));
}
// VT tiles: 256B rows (128 keys bf16), swizzle within each 128B half
__device__ __forceinline__ uint32_t vswz(int h, int kb){
    return (uint32_t)(h*256 + (kb & 128) + ((kb & 127) ^ ((h & 7) << 4)));
}

typedef wmma::fragment<wmma::matrix_a, 16,16,16, __nv_bfloat16, wmma::row_major> FragA;
typedef wmma::fragment<wmma::matrix_b, 16,16,16, __nv_bfloat16, wmma::col_major> FragBc;
typedef wmma::fragment<wmma::accumulator, 16,16,16, float> FragC;

// ---------------------------------------------------------------------------
// K1: fused QKV projection (x read once) -> preformatted tiles.
// ---------------------------------------------------------------------------
#define PX_XHI 0
#define PX_XLO 16384
#define PX_WHI 32768
#define PX_WLO 57344
#define PX_STG 81920
#define SMEM_PROJ 114688

__global__ __launch_bounds__(256, 1) void proj_kernel(
    const float* __restrict__ x,
    const float* __restrict__ Wq,
    const float* __restrict__ Wk,
    const float* __restrict__ Wv)
{
    extern __shared__ char sm[];
    __nv_bfloat16* xhi = (__nv_bfloat16*)(sm + PX_XHI);
    __nv_bfloat16* xlo = (__nv_bfloat16*)(sm + PX_XLO);
    float* stg = (float*)(sm + PX_STG);

    const float* Wm[3] = {Wq, Wk, Wv};
    const int tile = blockIdx.x;
    const int row0 = tile * 128;
    const int tid  = threadIdx.x;
    const int w    = tid >> 5;

    if (tile == 0 && tid == 0) g_ent = 0.0f;

    FragC acc[3][4];
    #pragma unroll
    for (int m = 0; m < 3; m++)
        #pragma unroll
        for (int n = 0; n < 4; n++) wmma::fill_fragment(acc[m][n], 0.0f);

    for (int c0 = 0; c0 < DMODEL; c0 += 64) {
        __syncthreads();
        #pragma unroll
        for (int i = 0; i < 16; i++) {
            int p = i*256 + tid;
            int r = p >> 5, c2 = p & 31;
            float2 v = *(const float2*)&x[(size_t)(row0 + r)*DMODEL + c0 + 2*c2];
            uint32_t u = pk2(v.x, v.y);
            ((uint32_t*)xhi)[r*32 + c2] = u;
            ((uint32_t*)xlo)[r*32 + c2] = pk2lo(v.x, v.y, u);
        }
        #pragma unroll
        for (int m = 0; m < 3; m++) {
            __nv_bfloat16* whi = (__nv_bfloat16*)(sm + PX_WHI + m*8192);
            __nv_bfloat16* wlo = (__nv_bfloat16*)(sm + PX_WLO + m*8192);
            #pragma unroll
            for (int i = 0; i < 8; i++) {
                int p = i*256 + tid;
                int h = p >> 5, c2 = p & 31;
                float2 v = *(const float2*)&Wm[m][(size_t)h*DMODEL + c0 + 2*c2];
                uint32_t u = pk2(v.x, v.y);
                ((uint32_t*)whi)[h*32 + c2] = u;
                ((uint32_t*)wlo)[h*32 + c2] = pk2lo(v.x, v.y, u);
            }
        }
        __syncthreads();
        #pragma unroll
        for (int t = 0; t < 3; t++) {
            const __nv_bfloat16* A = (t == 2) ? xlo : xhi;
            #pragma unroll
            for (int kk = 0; kk < 4; kk++) {
                FragA af;
                wmma::load_matrix_sync(af, A + (16*w)*64 + kk*16, 64);
                #pragma unroll
                for (int m = 0; m < 3; m++) {
                    const __nv_bfloat16* B = (__nv_bfloat16*)(sm + ((t == 1) ? PX_WLO : PX_WHI) + m*8192);
                    #pragma unroll
                    for (int n = 0; n < 4; n++) {
                        FragBc bf;
                        wmma::load_matrix_sync(bf, B + (n*16)*64 + kk*16, 64);
                        wmma::mma_sync(acc[m][n], af, bf, acc[m][n]);
                    }
                }
            }
        }
    }

    #pragma unroll
    for (int m = 0; m < 3; m++) {
        __syncthreads();
        #pragma unroll
        for (int n = 0; n < 4; n++)
            wmma::store_matrix_sync(stg + (16*w)*64 + n*16, acc[m][n], 64, wmma::mem_row_major);
        __syncthreads();
        if (m < 2) {
            const float sc = (m == 0) ? SCALE_Q : 1.0f;
            char* dhi = (char*)((m == 0) ? g_qhi : g_khi) + (size_t)tile*16384;
            char* dlo = (char*)((m == 0) ? g_qlo : g_klo) + (size_t)tile*16384;
            #pragma unroll
            for (int i = 0; i < 16; i++) {
                int p = i*256 + tid;
                int r = p >> 5, c2 = p & 31;
                float f0 = stg[r*64 + 2*c2] * sc;
                float f1 = stg[r*64 + 2*c2 + 1] * sc;
                uint32_t off = swz(r, c2*4);
                uint32_t u = pk2(f0, f1);
                *(uint32_t*)(dhi + off) = u;
                *(uint32_t*)(dlo + off) = pk2lo(f0, f1, u);
            }
        } else {
            char* dhi = (char*)g_vthi + (size_t)tile*16384;
            char* dlo = (char*)g_vtlo + (size_t)tile*16384;
            int h = tid & 63, kp0 = tid >> 6;
            #pragma unroll
            for (int i = 0; i < 16; i++) {
                int pi = kp0 + 4*i;
                int k = 2*pi;
                float v0 = stg[k*64 + h];
                float v1 = stg[(k+1)*64 + h];
                uint32_t off = vswz(h, 4*pi);
                uint32_t u = pk2(v0, v1);
                *(uint32_t*)(dhi + off) = u;
                *(uint32_t*)(dlo + off) = pk2lo(v0, v1, u);
            }
        }
    }
}

// ---------------------------------------------------------------------------
// K2: fused attention, two-pass:
//   pass A: Z rowsums via 1-term bf16 S (khi only)
//   pass B: 3-term S, write normalized P once, entropy, O = P V (normalized)
// grid (32, 4), 256 threads. Chunk = 128 keys.
// ---------------------------------------------------------------------------
#define OQHI 0
#define OQLO 16384
#define OBUF 32768            // pass A: 2 x 16KB | pass B: 2 x 64KB
#define SMEM_ATTN 163840

__global__ __launch_bounds__(256, 1) void attn2_kernel(float* __restrict__ attn,
                                                       float* __restrict__ out)
{
    extern __shared__ char sm[];
    __shared__ float s_ent[8];

    const int tid  = threadIdx.x;
    const int w    = tid >> 5;
    const int lane = tid & 31;
    const int g    = lane >> 2;
    const int tq   = lane & 3;
    const int b    = blockIdx.y;
    const int q0   = blockIdx.x * 128;
    const size_t rowg = (size_t)b*TSEQ + q0;
    const int wr  = 16 * w;
    const uint32_t smb = smem_u32(sm);

    const int tile_q  = b*(TSEQ/128) + blockIdx.x;
    const int tile_k0 = b*(TSEQ/128);

    // ---- async copy Q tile (hi+lo) and pass-A chunk 0 (khi only) ----
    {
        const char* gq_hi = (const char*)g_qhi + (size_t)tile_q*16384;
        const char* gq_lo = (const char*)g_qlo + (size_t)tile_q*16384;
        #pragma unroll
        for (int i = 0; i < 4; i++) {
            uint32_t off = (uint32_t)(i*4096 + tid*16);
            cpa16(smb + OQHI + off, gq_hi + off);
            cpa16(smb + OQLO + off, gq_lo + off);
        }
        const char* gk_hi = (const char*)g_khi + (size_t)tile_k0*16384;
        #pragma unroll
        for (int i = 0; i < 4; i++) {
            uint32_t off = (uint32_t)(i*4096 + tid*16);
            cpa16(smb + OBUF + off, gk_hi + off);
        }
        CPA_COMMIT();
        CPA_WAIT0();
    }
    __syncthreads();

    // ---- Q fragments, held in registers ----
    uint32_t qh[4][4], ql[4][4];
    #pragma unroll
    for (int ks = 0; ks < 4; ks++) {
        int kb = ks*32 + tq*4;
        qh[ks][0] = *(const uint32_t*)(sm + OQHI + swz(wr+g,   kb));
        qh[ks][1] = *(const uint32_t*)(sm + OQHI + swz(wr+g+8, kb));
        qh[ks][2] = *(const uint32_t*)(sm + OQHI + swz(wr+g,   kb+16));
        qh[ks][3] = *(const uint32_t*)(sm + OQHI + swz(wr+g+8, kb+16));
        ql[ks][0] = *(const uint32_t*)(sm + OQLO + swz(wr+g,   kb));
        ql[ks][1] = *(const uint32_t*)(sm + OQLO + swz(wr+g+8, kb));
        ql[ks][2] = *(const uint32_t*)(sm + OQLO + swz(wr+g,   kb+16));
        ql[ks][3] = *(const uint32_t*)(sm + OQLO + swz(wr+g+8, kb+16));
    }

    // ====================== PASS A: rowsums Z (1-term) ======================
    float Zr0 = 0.f, Zr1 = 0.f;
    for (int c = 0; c < TSEQ/128; c++) {
        __syncthreads();
        if (c < TSEQ/128 - 1) {
            const char* gk_hi = (const char*)g_khi + (size_t)(tile_k0 + c + 1)*16384;
            const uint32_t dst = smb + OBUF + (uint32_t)(((c+1)&1)*16384);
            #pragma unroll
            for (int i = 0; i < 4; i++) {
                uint32_t off = (uint32_t)(i*4096 + tid*16);
                cpa16(dst + off, gk_hi + off);
            }
            CPA_COMMIT();
            CPA_WAIT1();
        } else {
            CPA_WAIT0();
        }
        __syncthreads();

        const char* bk = sm + OBUF + (c&1)*16384;
        float sacc[16][4];
        #pragma unroll
        for (int n = 0; n < 16; n++)
            #pragma unroll
            for (int j = 0; j < 4; j++) sacc[n][j] = 0.0f;
        #pragma unroll
        for (int nt = 0; nt < 16; nt++) {
            #pragma unroll
            for (int ks = 0; ks < 4; ks++) {
                int kb = ks*32 + tq*4;
                int kr = nt*8 + g;
                uint32_t bh0 = *(const uint32_t*)(bk + swz(kr, kb));
                uint32_t bh1 = *(const uint32_t*)(bk + swz(kr, kb+16));
                mma16816(sacc[nt], qh[ks], bh0, bh1);
            }
        }
        #pragma unroll
        for (int nt = 0; nt < 16; nt++) {
            Zr0 += ex2f_(sacc[nt][0]) + ex2f_(sacc[nt][1]);
            Zr1 += ex2f_(sacc[nt][2]) + ex2f_(sacc[nt][3]);
        }
    }
    #pragma unroll
    for (int off = 1; off <= 2; off <<= 1) {
        Zr0 += __shfl_xor_sync(0xffffffffu, Zr0, off);
        Zr1 += __shfl_xor_sync(0xffffffffu, Zr1, off);
    }
    const float lz0 = lg2f_(Zr0);
    const float lz1 = lg2f_(Zr1);

    // ================== PASS B: normalized P write + O = P V =================
    float oacc[8][4];
    #pragma unroll
    for (int n = 0; n < 8; n++)
        #pragma unroll
        for (int j = 0; j < 4; j++) oacc[n][j] = 0.0f;
    float eacc = 0.0f;

    __syncthreads();
    {
        const size_t tn = (size_t)tile_k0*16384;
        #pragma unroll
        for (int i = 0; i < 4; i++) {
            uint32_t off = (uint32_t)(i*4096 + tid*16);
            cpa16(smb + OBUF + off,         (const char*)g_khi  + tn + off);
            cpa16(smb + OBUF + 16384 + off, (const char*)g_klo  + tn + off);
            cpa16(smb + OBUF + 32768 + off, (const char*)g_vthi + tn + off);
            cpa16(smb + OBUF + 49152 + off, (const char*)g_vtlo + tn + off);
        }
        CPA_COMMIT();
    }

    for (int c = 0; c < TSEQ/128; c++) {
        __syncthreads();
        if (c < TSEQ/128 - 1) {
            const size_t tn = (size_t)(tile_k0 + c + 1)*16384;
            const uint32_t dst = smb + OBUF + (uint32_t)(((c+1)&1)*65536);
            #pragma unroll
            for (int i = 0; i < 4; i++) {
                uint32_t off = (uint32_t)(i*4096 + tid*16);
                cpa16(dst + off,         (const char*)g_khi  + tn + off);
                cpa16(dst + 16384 + off, (const char*)g_klo  + tn + off);
                cpa16(dst + 32768 + off, (const char*)g_vthi + tn + off);
                cpa16(dst + 49152 + off, (const char*)g_vtlo + tn + off);
            }
            CPA_COMMIT();
            CPA_WAIT1();
        } else {
            CPA_WAIT0();
        }
        __syncthreads();

        const char* bk   = sm + OBUF + (c&1)*65536;
        const char* bklo = bk + 16384;
        const char* bv   = bk + 32768;
        const char* bvlo = bk + 49152;

        // ---- S = Q K^T (3-term) ----
        float sacc[16][4];
        #pragma unroll
        for (int n = 0; n < 16; n++)
            #pragma unroll
            for (int j = 0; j < 4; j++) sacc[n][j] = 0.0f;

        #pragma unroll
        for (int nt = 0; nt < 16; nt++) {
            #pragma unroll
            for (int ks = 0; ks < 4; ks++) {
                int kb = ks*32 + tq*4;
                int kr = nt*8 + g;
                uint32_t bh0 = *(const uint32_t*)(bk   + swz(kr, kb));
                uint32_t bh1 = *(const uint32_t*)(bk   + swz(kr, kb+16));
                uint32_t bl0 = *(const uint32_t*)(bklo + swz(kr, kb));
                uint32_t bl1 = *(const uint32_t*)(bklo + swz(kr, kb+16));
                mma16816(sacc[nt], qh[ks], bh0, bh1);
                mma16816(sacc[nt], qh[ks], bl0, bl1);
                mma16816(sacc[nt], ql[ks], bh0, bh1);
            }
        }

        // ---- normalized exp, entropy, attn store, P frags ----
        uint32_t ph[8][4], pl[8][4];
        float* arow0 = attn + (rowg + wr + g)*TSEQ + c*128 + 2*tq;
        float* arow1 = arow0 + (size_t)8*TSEQ;
        #pragma unroll
        for (int ks = 0; ks < 8; ks++) {
            #pragma unroll
            for (int h2 = 0; h2 < 2; h2++) {
                int nt = 2*ks + h2;
                float t0 = sacc[nt][0] - lz0, t1 = sacc[nt][1] - lz0;
                float t2 = sacc[nt][2] - lz1, t3 = sacc[nt][3] - lz1;
                float e0 = ex2f_(t0), e1 = ex2f_(t1), e2 = ex2f_(t2), e3 = ex2f_(t3);
                eacc += (e0*t0 + e1*t1) + (e2*t2 + e3*t3);
                *(float2*)(arow0 + nt*8) = make_float2(e0, e1);
                *(float2*)(arow1 + nt*8) = make_float2(e2, e3);
                uint32_t u01 = pk2(e0, e1), u23 = pk2(e2, e3);
                if (h2 == 0) {
                    ph[ks][0] = u01;                 ph[ks][1] = u23;
                    pl[ks][0] = pk2lo(e0, e1, u01);  pl[ks][1] = pk2lo(e2, e3, u23);
                } else {
                    ph[ks][2] = u01;                 ph[ks][3] = u23;
                    pl[ks][2] = pk2lo(e0, e1, u01);  pl[ks][3] = pk2lo(e2, e3, u23);
                }
            }
        }

        // ---- O += P V (P already normalized) ----
        #pragma unroll
        for (int nt = 0; nt < 8; nt++) {
            #pragma unroll
            for (int ks = 0; ks < 8; ks++) {
                int kb = ks*32 + tq*4;
                int h  = nt*8 + g;
                uint32_t vh0 = *(const uint32_t*)(bv   + vswz(h, kb));
                uint32_t vh1 = *(const uint32_t*)(bv   + vswz(h, kb+16));
                uint32_t vl0 = *(const uint32_t*)(bvlo + vswz(h, kb));
                uint32_t vl1 = *(const uint32_t*)(bvlo + vswz(h, kb+16));
                mma16816(oacc[nt], ph[ks], vh0, vh1);
                mma16816(oacc[nt], ph[ks], vl0, vl1);
                mma16816(oacc[nt], pl[ks], vh0, vh1);
            }
        }
    }

    // ---- O write (already normalized) ----
    float* orow0 = out + (rowg + wr + g)*HDIM + 2*tq;
    float* orow1 = orow0 + (size_t)8*HDIM;
    #pragma unroll
    for (int nt = 0; nt < 8; nt++) {
        *(float2*)(orow0 + nt*8) = make_float2(oacc[nt][0], oacc[nt][1]);
        *(float2*)(orow1 + nt*8) = make_float2(oacc[nt][2], oacc[nt][3]);
    }

    // ---- entropy: eacc = sum p*lg2(p); reduce, one atomicAdd per CTA ----
    #pragma unroll
    for (int off = 16; off > 0; off >>= 1)
        eacc += __shfl_xor_sync(0xffffffffu, eacc, off);
    if (lane == 0) s_ent[w] = eacc;
    __syncthreads();
    if (tid == 0) {
        float t = 0.0f;
        #pragma unroll
        for (int i = 0; i < 8; i++) t += s_ent[i];
        atomicAdd(&g_ent, t);
    }
}

// ---------------------------------------------------------------------------
// K3: finalize energy EMA.  H_mean = -ln2 * g_ent / NROWS
// ---------------------------------------------------------------------------
__global__ void fin_kernel(const float* __restrict__ energy, float* __restrict__ eout)
{
    float ent_mean = -0.6931471805599453f * g_ent / (float)NROWS;
    *eout = 0.9f * energy[0] + 0.1f * ent_mean;
}

// ---------------------------------------------------------------------------
extern "C" void kernel_launch(void* const* d_in, const int* in_sizes, int n_in,
                              void* d_out, int out_size)
{
    const float* x      = (const float*)d_in[0];
    const float* Wq     = (const float*)d_in[1];
    const float* Wk     = (const float*)d_in[2];
    const float* Wv     = (const float*)d_in[3];
    const float* energy = (const float*)d_in[4];

    float* out  = (float*)d_out;                               // [B,T,H]
    float* attn = out + (size_t)BATCH*TSEQ*HDIM;               // [B,T,T]
    float* eout = attn + (size_t)BATCH*TSEQ*TSEQ;              // scalar

    cudaFuncSetAttribute(proj_kernel,  cudaFuncAttributeMaxDynamicSharedMemorySize, SMEM_PROJ);
    cudaFuncSetAttribute(attn2_kernel, cudaFuncAttributeMaxDynamicSharedMemorySize, SMEM_ATTN);

    proj_kernel<<<NTILE, 256, SMEM_PROJ>>>(x, Wq, Wk, Wv);
    attn2_kernel<<<dim3(TSEQ/128, BATCH), 256, SMEM_ATTN>>>(attn, out);
    fin_kernel<<<1, 1>>>(energy, eout);
}

// round 9
// speedup vs baseline: 4.0135x; 1.6114x over previous
#include <cuda_runtime.h>
#include <cuda_bf16.h>
#include <math.h>
#include <stdint.h>

#define BATCH 4
#define TSEQ  4096
#define DMODEL 1024
#define HDIM  64
#define NROWS (BATCH*TSEQ)
#define NTILE (NROWS/128)

#define SCALE_Q 0.18033688011112042f   // log2(e)/8

// Scratch: preformatted bf16 hi/lo tiles (swizzled smem images)
__device__ __align__(16) __nv_bfloat16 g_qhi[NROWS*HDIM];
__device__ __align__(16) __nv_bfloat16 g_qlo[NROWS*HDIM];
__device__ __align__(16) __nv_bfloat16 g_khi[NROWS*HDIM];
__device__ __align__(16) __nv_bfloat16 g_klo[NROWS*HDIM];
__device__ __align__(16) __nv_bfloat16 g_vthi[NROWS*HDIM];
__device__ __align__(16) __nv_bfloat16 g_vtlo[NROWS*HDIM];
__device__ float g_ent;

__device__ __forceinline__ float ex2f_(float x){ float y; asm("ex2.approx.ftz.f32 %0, %1;" : "=f"(y) : "f"(x)); return y; }
__device__ __forceinline__ float lg2f_(float x){ float y; asm("lg2.approx.f32 %0, %1;" : "=f"(y) : "f"(x)); return y; }

// pack (a -> low half, b -> high half) as bf16x2 in one cvt
__device__ __forceinline__ uint32_t pk2(float a, float b){
    uint32_t r;
    asm("cvt.rn.bf16x2.f32 %0, %1, %2;" : "=r"(r) : "f"(b), "f"(a));
    return r;
}
// residuals of a packed pair: lo parts of (a,b) given u = pk2(a,b)
__device__ __forceinline__ uint32_t pk2lo(float a, float b, uint32_t u){
    float hi_a = __uint_as_float(u << 16);
    float hi_b = __uint_as_float(u & 0xffff0000u);
    return pk2(a - hi_a, b - hi_b);
}
__device__ __forceinline__ uint32_t smem_u32(const void* p){
    uint32_t a;
    asm("{ .reg .u64 t; cvta.to.shared.u64 t, %1; cvt.u32.u64 %0, t; }" : "=r"(a) : "l"(p));
    return a;
}
__device__ __forceinline__ void cpa16(uint32_t s, const void* g){
    asm volatile("cp.async.cg.shared.global [%0], [%1], 16;" :: "r"(s), "l"(g));
}
#define CPA_COMMIT() asm volatile("cp.async.commit_group;" ::: "memory")
#define CPA_WAIT0()  asm volatile("cp.async.wait_group 0;" ::: "memory")
#define CPA_WAIT1()  asm volatile("cp.async.wait_group 1;" ::: "memory")

__device__ __forceinline__ void mma16816(float* c, const uint32_t* a, uint32_t b0, uint32_t b1){
    asm volatile("mma.sync.aligned.m16n8k16.row.col.f32.bf16.bf16.f32 "
        "{%0,%1,%2,%3}, {%4,%5,%6,%7}, {%8,%9}, {%0,%1,%2,%3};"
        : "+f"(c[0]), "+f"(c[1]), "+f"(c[2]), "+f"(c[3])
        : "r"(a[0]), "r"(a[1]), "r"(a[2]), "r"(a[3]), "r"(b0), "r"(b1));
}

// Q/K/W tiles: 128B rows, row r, byte col cb (0..127)
__device__ __forceinline__ uint32_t swz(int r, int cb){
    return (uint32_t)(r*128 + (cb ^ ((r & 7) << 4)));
}
// VT tiles: 256B rows (128 keys bf16), swizzle within each 128B half
__device__ __forceinline__ uint32_t vswz(int h, int kb){
    return (uint32_t)(h*256 + (kb & 128) + ((kb & 127) ^ ((h & 7) << 4)));
}

// ---------------------------------------------------------------------------
// K1: fused QKV projection, raw mma.sync, swizzled smem, register epilogue.
// grid 128, block 256 (8 warps x 16 rows). K-chunk = 64.
// ---------------------------------------------------------------------------
#define PX_XHI 0
#define PX_XLO 16384
#define PX_W   32768           // 3 x (whi 8KB + wlo 8KB) = 48KB
#define SMEM_PROJ 81920
#define PSTG_STRIDE 66         // fp32 staging stride (pad vs 64 to avoid conflicts)

__global__ __launch_bounds__(256, 1) void proj_kernel(
    const float* __restrict__ x,
    const float* __restrict__ Wq,
    const float* __restrict__ Wk,
    const float* __restrict__ Wv)
{
    extern __shared__ char sm[];
    const float* Wm[3] = {Wq, Wk, Wv};

    const int tile = blockIdx.x;
    const int row0 = tile * 128;
    const int tid  = threadIdx.x;
    const int w    = tid >> 5;
    const int lane = tid & 31;
    const int g    = lane >> 2;
    const int tq   = lane & 3;
    const int wr   = 16 * w;

    if (tile == 0 && tid == 0) g_ent = 0.0f;

    float acc[3][8][4];
    #pragma unroll
    for (int m = 0; m < 3; m++)
        #pragma unroll
        for (int n = 0; n < 8; n++)
            #pragma unroll
            for (int j = 0; j < 4; j++) acc[m][n][j] = 0.0f;

    for (int c0 = 0; c0 < DMODEL; c0 += 64) {
        __syncthreads();
        // x chunk 128x64 -> swizzled bf16 hi/lo
        #pragma unroll
        for (int i = 0; i < 16; i++) {
            int p = i*256 + tid;
            int r = p >> 5, c2 = p & 31;
            float2 v = *(const float2*)&x[(size_t)(row0 + r)*DMODEL + c0 + 2*c2];
            uint32_t u = pk2(v.x, v.y);
            uint32_t off = swz(r, c2*4);
            *(uint32_t*)(sm + PX_XHI + off) = u;
            *(uint32_t*)(sm + PX_XLO + off) = pk2lo(v.x, v.y, u);
        }
        // W chunks 3 x 64x64 -> swizzled bf16 hi/lo
        #pragma unroll
        for (int m = 0; m < 3; m++) {
            char* whi = sm + PX_W + m*16384;
            char* wlo = whi + 8192;
            #pragma unroll
            for (int i = 0; i < 8; i++) {
                int p = i*256 + tid;
                int h = p >> 5, c2 = p & 31;
                float2 v = *(const float2*)&Wm[m][(size_t)h*DMODEL + c0 + 2*c2];
                uint32_t u = pk2(v.x, v.y);
                uint32_t off = swz(h, c2*4);
                *(uint32_t*)(whi + off) = u;
                *(uint32_t*)(wlo + off) = pk2lo(v.x, v.y, u);
            }
        }
        __syncthreads();

        #pragma unroll
        for (int ks = 0; ks < 4; ks++) {
            int kb = ks*32 + tq*4;
            uint32_t ah[4], al[4];
            ah[0] = *(const uint32_t*)(sm + PX_XHI + swz(wr+g,   kb));
            ah[1] = *(const uint32_t*)(sm + PX_XHI + swz(wr+g+8, kb));
            ah[2] = *(const uint32_t*)(sm + PX_XHI + swz(wr+g,   kb+16));
            ah[3] = *(const uint32_t*)(sm + PX_XHI + swz(wr+g+8, kb+16));
            al[0] = *(const uint32_t*)(sm + PX_XLO + swz(wr+g,   kb));
            al[1] = *(const uint32_t*)(sm + PX_XLO + swz(wr+g+8, kb));
            al[2] = *(const uint32_t*)(sm + PX_XLO + swz(wr+g,   kb+16));
            al[3] = *(const uint32_t*)(sm + PX_XLO + swz(wr+g+8, kb+16));
            #pragma unroll
            for (int m = 0; m < 3; m++) {
                const char* whi = sm + PX_W + m*16384;
                const char* wlo = whi + 8192;
                #pragma unroll
                for (int nt = 0; nt < 8; nt++) {
                    int hr = nt*8 + g;
                    uint32_t bh0 = *(const uint32_t*)(whi + swz(hr, kb));
                    uint32_t bh1 = *(const uint32_t*)(whi + swz(hr, kb+16));
                    uint32_t bl0 = *(const uint32_t*)(wlo + swz(hr, kb));
                    uint32_t bl1 = *(const uint32_t*)(wlo + swz(hr, kb+16));
                    mma16816(acc[m][nt], ah, bh0, bh1);
                    mma16816(acc[m][nt], ah, bl0, bl1);
                    mma16816(acc[m][nt], al, bh0, bh1);
                }
            }
        }
    }

    // ---- epilogue: Q,K straight from registers to gmem tiles ----
    #pragma unroll
    for (int m = 0; m < 2; m++) {
        const float sc = (m == 0) ? SCALE_Q : 1.0f;
        char* dhi = (char*)((m == 0) ? g_qhi : g_khi) + (size_t)tile*16384;
        char* dlo = (char*)((m == 0) ? g_qlo : g_klo) + (size_t)tile*16384;
        #pragma unroll
        for (int nt = 0; nt < 8; nt++) {
            float c0 = acc[m][nt][0]*sc, c1 = acc[m][nt][1]*sc;
            float c2 = acc[m][nt][2]*sc, c3 = acc[m][nt][3]*sc;
            int cb = nt*16 + tq*4;
            uint32_t u0 = pk2(c0, c1), u1 = pk2(c2, c3);
            *(uint32_t*)(dhi + swz(wr+g,   cb)) = u0;
            *(uint32_t*)(dhi + swz(wr+g+8, cb)) = u1;
            *(uint32_t*)(dlo + swz(wr+g,   cb)) = pk2lo(c0, c1, u0);
            *(uint32_t*)(dlo + swz(wr+g+8, cb)) = pk2lo(c2, c3, u1);
        }
    }

    // ---- V: stage fp32 (padded stride), transpose, write VT tiles ----
    __syncthreads();                    // x/W smem dead; reuse as staging
    float* stg = (float*)sm;            // [128][PSTG_STRIDE]
    #pragma unroll
    for (int nt = 0; nt < 8; nt++) {
        int hc = nt*8 + tq*2;
        *(float2*)&stg[(wr+g)*PSTG_STRIDE + hc]   = make_float2(acc[2][nt][0], acc[2][nt][1]);
        *(float2*)&stg[(wr+g+8)*PSTG_STRIDE + hc] = make_float2(acc[2][nt][2], acc[2][nt][3]);
    }
    __syncthreads();
    {
        char* dhi = (char*)g_vthi + (size_t)tile*16384;
        char* dlo = (char*)g_vtlo + (size_t)tile*16384;
        int h = tid & 63, kp0 = tid >> 6;
        #pragma unroll
        for (int i = 0; i < 16; i++) {
            int pi = kp0 + 4*i;
            int k = 2*pi;
            float v0 = stg[k*PSTG_STRIDE + h];
            float v1 = stg[(k+1)*PSTG_STRIDE + h];
            uint32_t off = vswz(h, 4*pi);
            uint32_t u = pk2(v0, v1);
            *(uint32_t*)(dhi + off) = u;
            *(uint32_t*)(dlo + off) = pk2lo(v0, v1, u);
        }
    }
}

// ---------------------------------------------------------------------------
// K2: fused attention, two-pass (unchanged from R8, passing at 3.85e-4):
//   pass A: Z rowsums via 1-term bf16 S (khi only)
//   pass B: 3-term S, write normalized P once, entropy, O = P V
// ---------------------------------------------------------------------------
#define OQHI 0
#define OQLO 16384
#define OBUF 32768
#define SMEM_ATTN 163840

__global__ __launch_bounds__(256, 1) void attn2_kernel(float* __restrict__ attn,
                                                       float* __restrict__ out)
{
    extern __shared__ char sm[];
    __shared__ float s_ent[8];

    const int tid  = threadIdx.x;
    const int w    = tid >> 5;
    const int lane = tid & 31;
    const int g    = lane >> 2;
    const int tq   = lane & 3;
    const int b    = blockIdx.y;
    const int q0   = blockIdx.x * 128;
    const size_t rowg = (size_t)b*TSEQ + q0;
    const int wr  = 16 * w;
    const uint32_t smb = smem_u32(sm);

    const int tile_q  = b*(TSEQ/128) + blockIdx.x;
    const int tile_k0 = b*(TSEQ/128);

    {
        const char* gq_hi = (const char*)g_qhi + (size_t)tile_q*16384;
        const char* gq_lo = (const char*)g_qlo + (size_t)tile_q*16384;
        #pragma unroll
        for (int i = 0; i < 4; i++) {
            uint32_t off = (uint32_t)(i*4096 + tid*16);
            cpa16(smb + OQHI + off, gq_hi + off);
            cpa16(smb + OQLO + off, gq_lo + off);
        }
        const char* gk_hi = (const char*)g_khi + (size_t)tile_k0*16384;
        #pragma unroll
        for (int i = 0; i < 4; i++) {
            uint32_t off = (uint32_t)(i*4096 + tid*16);
            cpa16(smb + OBUF + off, gk_hi + off);
        }
        CPA_COMMIT();
        CPA_WAIT0();
    }
    __syncthreads();

    uint32_t qh[4][4], ql[4][4];
    #pragma unroll
    for (int ks = 0; ks < 4; ks++) {
        int kb = ks*32 + tq*4;
        qh[ks][0] = *(const uint32_t*)(sm + OQHI + swz(wr+g,   kb));
        qh[ks][1] = *(const uint32_t*)(sm + OQHI + swz(wr+g+8, kb));
        qh[ks][2] = *(const uint32_t*)(sm + OQHI + swz(wr+g,   kb+16));
        qh[ks][3] = *(const uint32_t*)(sm + OQHI + swz(wr+g+8, kb+16));
        ql[ks][0] = *(const uint32_t*)(sm + OQLO + swz(wr+g,   kb));
        ql[ks][1] = *(const uint32_t*)(sm + OQLO + swz(wr+g+8, kb));
        ql[ks][2] = *(const uint32_t*)(sm + OQLO + swz(wr+g,   kb+16));
        ql[ks][3] = *(const uint32_t*)(sm + OQLO + swz(wr+g+8, kb+16));
    }

    // ====================== PASS A: rowsums Z (1-term) ======================
    float Zr0 = 0.f, Zr1 = 0.f;
    for (int c = 0; c < TSEQ/128; c++) {
        __syncthreads();
        if (c < TSEQ/128 - 1) {
            const char* gk_hi = (const char*)g_khi + (size_t)(tile_k0 + c + 1)*16384;
            const uint32_t dst = smb + OBUF + (uint32_t)(((c+1)&1)*16384);
            #pragma unroll
            for (int i = 0; i < 4; i++) {
                uint32_t off = (uint32_t)(i*4096 + tid*16);
                cpa16(dst + off, gk_hi + off);
            }
            CPA_COMMIT();
            CPA_WAIT1();
        } else {
            CPA_WAIT0();
        }
        __syncthreads();

        const char* bk = sm + OBUF + (c&1)*16384;
        float sacc[16][4];
        #pragma unroll
        for (int n = 0; n < 16; n++)
            #pragma unroll
            for (int j = 0; j < 4; j++) sacc[n][j] = 0.0f;
        #pragma unroll
        for (int nt = 0; nt < 16; nt++) {
            #pragma unroll
            for (int ks = 0; ks < 4; ks++) {
                int kb = ks*32 + tq*4;
                int kr = nt*8 + g;
                uint32_t bh0 = *(const uint32_t*)(bk + swz(kr, kb));
                uint32_t bh1 = *(const uint32_t*)(bk + swz(kr, kb+16));
                mma16816(sacc[nt], qh[ks], bh0, bh1);
            }
        }
        #pragma unroll
        for (int nt = 0; nt < 16; nt++) {
            Zr0 += ex2f_(sacc[nt][0]) + ex2f_(sacc[nt][1]);
            Zr1 += ex2f_(sacc[nt][2]) + ex2f_(sacc[nt][3]);
        }
    }
    #pragma unroll
    for (int off = 1; off <= 2; off <<= 1) {
        Zr0 += __shfl_xor_sync(0xffffffffu, Zr0, off);
        Zr1 += __shfl_xor_sync(0xffffffffu, Zr1, off);
    }
    const float lz0 = lg2f_(Zr0);
    const float lz1 = lg2f_(Zr1);

    // ================== PASS B: normalized P write + O = P V =================
    float oacc[8][4];
    #pragma unroll
    for (int n = 0; n < 8; n++)
        #pragma unroll
        for (int j = 0; j < 4; j++) oacc[n][j] = 0.0f;
    float eacc = 0.0f;

    __syncthreads();
    {
        const size_t tn = (size_t)tile_k0*16384;
        #pragma unroll
        for (int i = 0; i < 4; i++) {
            uint32_t off = (uint32_t)(i*4096 + tid*16);
            cpa16(smb + OBUF + off,         (const char*)g_khi  + tn + off);
            cpa16(smb + OBUF + 16384 + off, (const char*)g_klo  + tn + off);
            cpa16(smb + OBUF + 32768 + off, (const char*)g_vthi + tn + off);
            cpa16(smb + OBUF + 49152 + off, (const char*)g_vtlo + tn + off);
        }
        CPA_COMMIT();
    }

    for (int c = 0; c < TSEQ/128; c++) {
        __syncthreads();
        if (c < TSEQ/128 - 1) {
            const size_t tn = (size_t)(tile_k0 + c + 1)*16384;
            const uint32_t dst = smb + OBUF + (uint32_t)(((c+1)&1)*65536);
            #pragma unroll
            for (int i = 0; i < 4; i++) {
                uint32_t off = (uint32_t)(i*4096 + tid*16);
                cpa16(dst + off,         (const char*)g_khi  + tn + off);
                cpa16(dst + 16384 + off, (const char*)g_klo  + tn + off);
                cpa16(dst + 32768 + off, (const char*)g_vthi + tn + off);
                cpa16(dst + 49152 + off, (const char*)g_vtlo + tn + off);
            }
            CPA_COMMIT();
            CPA_WAIT1();
        } else {
            CPA_WAIT0();
        }
        __syncthreads();

        const char* bk   = sm + OBUF + (c&1)*65536;
        const char* bklo = bk + 16384;
        const char* bv   = bk + 32768;
        const char* bvlo = bk + 49152;

        float sacc[16][4];
        #pragma unroll
        for (int n = 0; n < 16; n++)
            #pragma unroll
            for (int j = 0; j < 4; j++) sacc[n][j] = 0.0f;

        #pragma unroll
        for (int nt = 0; nt < 16; nt++) {
            #pragma unroll
            for (int ks = 0; ks < 4; ks++) {
                int kb = ks*32 + tq*4;
                int kr = nt*8 + g;
                uint32_t bh0 = *(const uint32_t*)(bk   + swz(kr, kb));
                uint32_t bh1 = *(const uint32_t*)(bk   + swz(kr, kb+16));
                uint32_t bl0 = *(const uint32_t*)(bklo + swz(kr, kb));
                uint32_t bl1 = *(const uint32_t*)(bklo + swz(kr, kb+16));
                mma16816(sacc[nt], qh[ks], bh0, bh1);
                mma16816(sacc[nt], qh[ks], bl0, bl1);
                mma16816(sacc[nt], ql[ks], bh0, bh1);
            }
        }

        uint32_t ph[8][4], pl[8][4];
        float* arow0 = attn + (rowg + wr + g)*TSEQ + c*128 + 2*tq;
        float* arow1 = arow0 + (size_t)8*TSEQ;
        #pragma unroll
        for (int ks = 0; ks < 8; ks++) {
            #pragma unroll
            for (int h2 = 0; h2 < 2; h2++) {
                int nt = 2*ks + h2;
                float t0 = sacc[nt][0] - lz0, t1 = sacc[nt][1] - lz0;
                float t2 = sacc[nt][2] - lz1, t3 = sacc[nt][3] - lz1;
                float e0 = ex2f_(t0), e1 = ex2f_(t1), e2 = ex2f_(t2), e3 = ex2f_(t3);
                eacc += (e0*t0 + e1*t1) + (e2*t2 + e3*t3);
                *(float2*)(arow0 + nt*8) = make_float2(e0, e1);
                *(float2*)(arow1 + nt*8) = make_float2(e2, e3);
                uint32_t u01 = pk2(e0, e1), u23 = pk2(e2, e3);
                if (h2 == 0) {
                    ph[ks][0] = u01;                 ph[ks][1] = u23;
                    pl[ks][0] = pk2lo(e0, e1, u01);  pl[ks][1] = pk2lo(e2, e3, u23);
                } else {
                    ph[ks][2] = u01;                 ph[ks][3] = u23;
                    pl[ks][2] = pk2lo(e0, e1, u01);  pl[ks][3] = pk2lo(e2, e3, u23);
                }
            }
        }

        #pragma unroll
        for (int nt = 0; nt < 8; nt++) {
            #pragma unroll
            for (int ks = 0; ks < 8; ks++) {
                int kb = ks*32 + tq*4;
                int h  = nt*8 + g;
                uint32_t vh0 = *(const uint32_t*)(bv   + vswz(h, kb));
                uint32_t vh1 = *(const uint32_t*)(bv   + vswz(h, kb+16));
                uint32_t vl0 = *(const uint32_t*)(bvlo + vswz(h, kb));
                uint32_t vl1 = *(const uint32_t*)(bvlo + vswz(h, kb+16));
                mma16816(oacc[nt], ph[ks], vh0, vh1);
                mma16816(oacc[nt], ph[ks], vl0, vl1);
                mma16816(oacc[nt], pl[ks], vh0, vh1);
            }
        }
    }

    float* orow0 = out + (rowg + wr + g)*HDIM + 2*tq;
    float* orow1 = orow0 + (size_t)8*HDIM;
    #pragma unroll
    for (int nt = 0; nt < 8; nt++) {
        *(float2*)(orow0 + nt*8) = make_float2(oacc[nt][0], oacc[nt][1]);
        *(float2*)(orow1 + nt*8) = make_float2(oacc[nt][2], oacc[nt][3]);
    }

    #pragma unroll
    for (int off = 16; off > 0; off >>= 1)
        eacc += __shfl_xor_sync(0xffffffffu, eacc, off);
    if (lane == 0) s_ent[w] = eacc;
    __syncthreads();
    if (tid == 0) {
        float t = 0.0f;
        #pragma unroll
        for (int i = 0; i < 8; i++) t += s_ent[i];
        atomicAdd(&g_ent, t);
    }
}

// ---------------------------------------------------------------------------
// K3: finalize energy EMA.  H_mean = -ln2 * g_ent / NROWS
// ---------------------------------------------------------------------------
__global__ void fin_kernel(const float* __restrict__ energy, float* __restrict__ eout)
{
    float ent_mean = -0.6931471805599453f * g_ent / (float)NROWS;
    *eout = 0.9f * energy[0] + 0.1f * ent_mean;
}

// ---------------------------------------------------------------------------
extern "C" void kernel_launch(void* const* d_in, const int* in_sizes, int n_in,
                              void* d_out, int out_size)
{
    const float* x      = (const float*)d_in[0];
    const float* Wq     = (const float*)d_in[1];
    const float* Wk     = (const float*)d_in[2];
    const float* Wv     = (const float*)d_in[3];
    const float* energy = (const float*)d_in[4];

    float* out  = (float*)d_out;                               // [B,T,H]
    float* attn = out + (size_t)BATCH*TSEQ*HDIM;               // [B,T,T]
    float* eout = attn + (size_t)BATCH*TSEQ*TSEQ;              // scalar

    cudaFuncSetAttribute(proj_kernel,  cudaFuncAttributeMaxDynamicSharedMemorySize, SMEM_PROJ);
    cudaFuncSetAttribute(attn2_kernel, cudaFuncAttributeMaxDynamicSharedMemorySize, SMEM_ATTN);

    proj_kernel<<<NTILE, 256, SMEM_PROJ>>>(x, Wq, Wk, Wv);
    attn2_kernel<<<dim3(TSEQ/128, BATCH), 256, SMEM_ATTN>>>(attn, out);
    fin_kernel<<<1, 1>>>(energy, eout);
}

// round 10
// speedup vs baseline: 4.3636x; 1.0872x over previous
#include <cuda_runtime.h>
#include <cuda_bf16.h>
#include <math.h>
#include <stdint.h>

#define BATCH 4
#define TSEQ  4096
#define DMODEL 1024
#define HDIM  64
#define NROWS (BATCH*TSEQ)
#define NTILE (NROWS/128)

#define SCALE_Q 0.18033688011112042f   // log2(e)/8

// Scratch: preformatted bf16 hi/lo tiles (swizzled smem images)
__device__ __align__(16) __nv_bfloat16 g_qhi[NROWS*HDIM];
__device__ __align__(16) __nv_bfloat16 g_qlo[NROWS*HDIM];
__device__ __align__(16) __nv_bfloat16 g_khi[NROWS*HDIM];
__device__ __align__(16) __nv_bfloat16 g_klo[NROWS*HDIM];
__device__ __align__(16) __nv_bfloat16 g_vthi[NROWS*HDIM];
__device__ __align__(16) __nv_bfloat16 g_vtlo[NROWS*HDIM];
__device__ float g_ent;

__device__ __forceinline__ float ex2f_(float x){ float y; asm("ex2.approx.ftz.f32 %0, %1;" : "=f"(y) : "f"(x)); return y; }
__device__ __forceinline__ float lg2f_(float x){ float y; asm("lg2.approx.f32 %0, %1;" : "=f"(y) : "f"(x)); return y; }

__device__ __forceinline__ uint32_t pk2(float a, float b){
    uint32_t r;
    asm("cvt.rn.bf16x2.f32 %0, %1, %2;" : "=r"(r) : "f"(b), "f"(a));
    return r;
}
__device__ __forceinline__ uint32_t pk2lo(float a, float b, uint32_t u){
    float hi_a = __uint_as_float(u << 16);
    float hi_b = __uint_as_float(u & 0xffff0000u);
    return pk2(a - hi_a, b - hi_b);
}
__device__ __forceinline__ uint32_t smem_u32(const void* p){
    uint32_t a;
    asm("{ .reg .u64 t; cvta.to.shared.u64 t, %1; cvt.u32.u64 %0, t; }" : "=r"(a) : "l"(p));
    return a;
}
__device__ __forceinline__ void cpa16(uint32_t s, const void* g){
    asm volatile("cp.async.cg.shared.global [%0], [%1], 16;" :: "r"(s), "l"(g));
}
#define CPA_COMMIT() asm volatile("cp.async.commit_group;" ::: "memory")
#define CPA_WAIT0()  asm volatile("cp.async.wait_group 0;" ::: "memory")
#define CPA_WAIT1()  asm volatile("cp.async.wait_group 1;" ::: "memory")

__device__ __forceinline__ void mma16816(float* c, const uint32_t* a, uint32_t b0, uint32_t b1){
    asm volatile("mma.sync.aligned.m16n8k16.row.col.f32.bf16.bf16.f32 "
        "{%0,%1,%2,%3}, {%4,%5,%6,%7}, {%8,%9}, {%0,%1,%2,%3};"
        : "+f"(c[0]), "+f"(c[1]), "+f"(c[2]), "+f"(c[3])
        : "r"(a[0]), "r"(a[1]), "r"(a[2]), "r"(a[3]), "r"(b0), "r"(b1));
}
__device__ __forceinline__ void ldsm4(uint32_t* r, uint32_t addr){
    asm volatile("ldmatrix.sync.aligned.m8n8.x4.shared.b16 {%0,%1,%2,%3}, [%4];"
        : "=r"(r[0]), "=r"(r[1]), "=r"(r[2]), "=r"(r[3]) : "r"(addr));
}

// Q/K/W tiles: 128B rows, row r, byte col cb (0..127)
__device__ __forceinline__ uint32_t swz(int r, int cb){
    return (uint32_t)(r*128 + (cb ^ ((r & 7) << 4)));
}
// VT tiles: 256B rows (128 keys bf16), swizzle within each 128B half
__device__ __forceinline__ uint32_t vswz(int h, int kb){
    return (uint32_t)(h*256 + (kb & 128) + ((kb & 127) ^ ((h & 7) << 4)));
}

// ---------------------------------------------------------------------------
// K1: fused QKV projection, raw mma.sync + ldmatrix, register epilogue.
// grid 128, block 256 (8 warps x 16 rows). K-chunk = 64.
// ---------------------------------------------------------------------------
#define PX_XHI 0
#define PX_XLO 16384
#define PX_W   32768           // 3 x (whi 8KB + wlo 8KB) = 48KB
#define SMEM_PROJ 81920
#define PSTG_STRIDE 66

__global__ __launch_bounds__(256, 1) void proj_kernel(
    const float* __restrict__ x,
    const float* __restrict__ Wq,
    const float* __restrict__ Wk,
    const float* __restrict__ Wv)
{
    extern __shared__ char sm[];
    const float* Wm[3] = {Wq, Wk, Wv};

    const int tile = blockIdx.x;
    const int row0 = tile * 128;
    const int tid  = threadIdx.x;
    const int w    = tid >> 5;
    const int lane = tid & 31;
    const int g    = lane >> 2;
    const int tq   = lane & 3;
    const int wr   = 16 * w;
    const uint32_t smb = smem_u32(sm);

    // ldmatrix per-lane constants (B operand: n16 pair x k16)
    const int      rip = ((lane >> 4) & 1)*8 + (lane & 7);
    const uint32_t khb = ((lane >> 3) & 1)*16;
    const uint32_t swl = (uint32_t)((lane & 7) << 4);
    // ldmatrix per-lane constants (A operand: m16 x k16)
    const int      ripA = ((lane >> 3) & 1)*8 + (lane & 7);
    const uint32_t khA  = (uint32_t)((lane >> 4) << 4);

    if (tile == 0 && tid == 0) g_ent = 0.0f;

    float acc[3][8][4];
    #pragma unroll
    for (int m = 0; m < 3; m++)
        #pragma unroll
        for (int n = 0; n < 8; n++)
            #pragma unroll
            for (int j = 0; j < 4; j++) acc[m][n][j] = 0.0f;

    for (int c0 = 0; c0 < DMODEL; c0 += 64) {
        __syncthreads();
        #pragma unroll
        for (int i = 0; i < 16; i++) {
            int p = i*256 + tid;
            int r = p >> 5, c2 = p & 31;
            float2 v = *(const float2*)&x[(size_t)(row0 + r)*DMODEL + c0 + 2*c2];
            uint32_t u = pk2(v.x, v.y);
            uint32_t off = swz(r, c2*4);
            *(uint32_t*)(sm + PX_XHI + off) = u;
            *(uint32_t*)(sm + PX_XLO + off) = pk2lo(v.x, v.y, u);
        }
        #pragma unroll
        for (int m = 0; m < 3; m++) {
            char* whi = sm + PX_W + m*16384;
            char* wlo = whi + 8192;
            #pragma unroll
            for (int i = 0; i < 8; i++) {
                int p = i*256 + tid;
                int h = p >> 5, c2 = p & 31;
                float2 v = *(const float2*)&Wm[m][(size_t)h*DMODEL + c0 + 2*c2];
                uint32_t u = pk2(v.x, v.y);
                uint32_t off = swz(h, c2*4);
                *(uint32_t*)(whi + off) = u;
                *(uint32_t*)(wlo + off) = pk2lo(v.x, v.y, u);
            }
        }
        __syncthreads();

        const uint32_t xrowA = smb + (uint32_t)((wr + ripA)*128);
        #pragma unroll
        for (int ks = 0; ks < 4; ks++) {
            uint32_t coA = ((uint32_t)(ks*32) | khA) ^ swl;
            uint32_t ah[4], al[4];
            ldsm4(ah, xrowA + PX_XHI + coA);
            ldsm4(al, xrowA + PX_XLO + coA);
            uint32_t co = ((uint32_t)(ks*32) | khb) ^ swl;
            #pragma unroll
            for (int m = 0; m < 3; m++) {
                #pragma unroll
                for (int ntp = 0; ntp < 4; ntp++) {
                    uint32_t rowb = smb + PX_W + (uint32_t)(m*16384 + (ntp*16 + rip)*128);
                    uint32_t bh[4], bl[4];
                    ldsm4(bh, rowb + co);
                    ldsm4(bl, rowb + 8192 + co);
                    mma16816(acc[m][2*ntp],   ah, bh[0], bh[1]);
                    mma16816(acc[m][2*ntp],   ah, bl[0], bl[1]);
                    mma16816(acc[m][2*ntp],   al, bh[0], bh[1]);
                    mma16816(acc[m][2*ntp+1], ah, bh[2], bh[3]);
                    mma16816(acc[m][2*ntp+1], ah, bl[2], bl[3]);
                    mma16816(acc[m][2*ntp+1], al, bh[2], bh[3]);
                }
            }
        }
    }

    // ---- epilogue: Q,K straight from registers to gmem tiles ----
    #pragma unroll
    for (int m = 0; m < 2; m++) {
        const float sc = (m == 0) ? SCALE_Q : 1.0f;
        char* dhi = (char*)((m == 0) ? g_qhi : g_khi) + (size_t)tile*16384;
        char* dlo = (char*)((m == 0) ? g_qlo : g_klo) + (size_t)tile*16384;
        #pragma unroll
        for (int nt = 0; nt < 8; nt++) {
            float c0 = acc[m][nt][0]*sc, c1 = acc[m][nt][1]*sc;
            float c2 = acc[m][nt][2]*sc, c3 = acc[m][nt][3]*sc;
            int cb = nt*16 + tq*4;
            uint32_t u0 = pk2(c0, c1), u1 = pk2(c2, c3);
            *(uint32_t*)(dhi + swz(wr+g,   cb)) = u0;
            *(uint32_t*)(dhi + swz(wr+g+8, cb)) = u1;
            *(uint32_t*)(dlo + swz(wr+g,   cb)) = pk2lo(c0, c1, u0);
            *(uint32_t*)(dlo + swz(wr+g+8, cb)) = pk2lo(c2, c3, u1);
        }
    }

    // ---- V: stage fp32 (padded stride), transpose, write VT tiles ----
    __syncthreads();
    float* stg = (float*)sm;
    #pragma unroll
    for (int nt = 0; nt < 8; nt++) {
        int hc = nt*8 + tq*2;
        *(float2*)&stg[(wr+g)*PSTG_STRIDE + hc]   = make_float2(acc[2][nt][0], acc[2][nt][1]);
        *(float2*)&stg[(wr+g+8)*PSTG_STRIDE + hc] = make_float2(acc[2][nt][2], acc[2][nt][3]);
    }
    __syncthreads();
    {
        char* dhi = (char*)g_vthi + (size_t)tile*16384;
        char* dlo = (char*)g_vtlo + (size_t)tile*16384;
        int h = tid & 63, kp0 = tid >> 6;
        #pragma unroll
        for (int i = 0; i < 16; i++) {
            int pi = kp0 + 4*i;
            int k = 2*pi;
            float v0 = stg[k*PSTG_STRIDE + h];
            float v1 = stg[(k+1)*PSTG_STRIDE + h];
            uint32_t off = vswz(h, 4*pi);
            uint32_t u = pk2(v0, v1);
            *(uint32_t*)(dhi + off) = u;
            *(uint32_t*)(dlo + off) = pk2lo(v0, v1, u);
        }
    }
}

// ---------------------------------------------------------------------------
// K2: fused attention, two-pass, ldmatrix B-operand loads.
//   pass A: Z rowsums via 1-term bf16 S (khi only)
//   pass B: 3-term S, write normalized P once, entropy, O = P V
// ---------------------------------------------------------------------------
#define OQHI 0
#define OQLO 16384
#define OBUF 32768
#define SMEM_ATTN 163840

__global__ __launch_bounds__(256, 1) void attn2_kernel(float* __restrict__ attn,
                                                       float* __restrict__ out)
{
    extern __shared__ char sm[];
    __shared__ float s_ent[8];

    const int tid  = threadIdx.x;
    const int w    = tid >> 5;
    const int lane = tid & 31;
    const int g    = lane >> 2;
    const int tq   = lane & 3;
    const int b    = blockIdx.y;
    const int q0   = blockIdx.x * 128;
    const size_t rowg = (size_t)b*TSEQ + q0;
    const int wr  = 16 * w;
    const uint32_t smb = smem_u32(sm);

    // ldmatrix per-lane constants
    const int      rip = ((lane >> 4) & 1)*8 + (lane & 7);
    const uint32_t khb = ((lane >> 3) & 1)*16;
    const uint32_t swl = (uint32_t)((lane & 7) << 4);

    const int tile_q  = b*(TSEQ/128) + blockIdx.x;
    const int tile_k0 = b*(TSEQ/128);

    {
        const char* gq_hi = (const char*)g_qhi + (size_t)tile_q*16384;
        const char* gq_lo = (const char*)g_qlo + (size_t)tile_q*16384;
        #pragma unroll
        for (int i = 0; i < 4; i++) {
            uint32_t off = (uint32_t)(i*4096 + tid*16);
            cpa16(smb + OQHI + off, gq_hi + off);
            cpa16(smb + OQLO + off, gq_lo + off);
        }
        const char* gk_hi = (const char*)g_khi + (size_t)tile_k0*16384;
        #pragma unroll
        for (int i = 0; i < 4; i++) {
            uint32_t off = (uint32_t)(i*4096 + tid*16);
            cpa16(smb + OBUF + off, gk_hi + off);
        }
        CPA_COMMIT();
        CPA_WAIT0();
    }
    __syncthreads();

    uint32_t qh[4][4], ql[4][4];
    #pragma unroll
    for (int ks = 0; ks < 4; ks++) {
        int kb = ks*32 + tq*4;
        qh[ks][0] = *(const uint32_t*)(sm + OQHI + swz(wr+g,   kb));
        qh[ks][1] = *(const uint32_t*)(sm + OQHI + swz(wr+g+8, kb));
        qh[ks][2] = *(const uint32_t*)(sm + OQHI + swz(wr+g,   kb+16));
        qh[ks][3] = *(const uint32_t*)(sm + OQHI + swz(wr+g+8, kb+16));
        ql[ks][0] = *(const uint32_t*)(sm + OQLO + swz(wr+g,   kb));
        ql[ks][1] = *(const uint32_t*)(sm + OQLO + swz(wr+g+8, kb));
        ql[ks][2] = *(const uint32_t*)(sm + OQLO + swz(wr+g,   kb+16));
        ql[ks][3] = *(const uint32_t*)(sm + OQLO + swz(wr+g+8, kb+16));
    }

    // ====================== PASS A: rowsums Z (1-term) ======================
    float Zr0 = 0.f, Zr1 = 0.f;
    for (int c = 0; c < TSEQ/128; c++) {
        __syncthreads();
        if (c < TSEQ/128 - 1) {
            const char* gk_hi = (const char*)g_khi + (size_t)(tile_k0 + c + 1)*16384;
            const uint32_t dst = smb + OBUF + (uint32_t)(((c+1)&1)*16384);
            #pragma unroll
            for (int i = 0; i < 4; i++) {
                uint32_t off = (uint32_t)(i*4096 + tid*16);
                cpa16(dst + off, gk_hi + off);
            }
            CPA_COMMIT();
            CPA_WAIT1();
        } else {
            CPA_WAIT0();
        }
        __syncthreads();

        const uint32_t kb32 = smb + OBUF + (uint32_t)((c&1)*16384);
        float sacc[16][4];
        #pragma unroll
        for (int n = 0; n < 16; n++)
            #pragma unroll
            for (int j = 0; j < 4; j++) sacc[n][j] = 0.0f;
        #pragma unroll
        for (int ntp = 0; ntp < 8; ntp++) {
            const uint32_t rowb = kb32 + (uint32_t)((ntp*16 + rip)*128);
            #pragma unroll
            for (int ks = 0; ks < 4; ks++) {
                uint32_t co = ((uint32_t)(ks*32) | khb) ^ swl;
                uint32_t bh[4];
                ldsm4(bh, rowb + co);
                mma16816(sacc[2*ntp],   qh[ks], bh[0], bh[1]);
                mma16816(sacc[2*ntp+1], qh[ks], bh[2], bh[3]);
            }
        }
        #pragma unroll
        for (int nt = 0; nt < 16; nt++) {
            Zr0 += ex2f_(sacc[nt][0]) + ex2f_(sacc[nt][1]);
            Zr1 += ex2f_(sacc[nt][2]) + ex2f_(sacc[nt][3]);
        }
    }
    #pragma unroll
    for (int off = 1; off <= 2; off <<= 1) {
        Zr0 += __shfl_xor_sync(0xffffffffu, Zr0, off);
        Zr1 += __shfl_xor_sync(0xffffffffu, Zr1, off);
    }
    const float lz0 = lg2f_(Zr0);
    const float lz1 = lg2f_(Zr1);

    // ================== PASS B: normalized P write + O = P V =================
    float oacc[8][4];
    #pragma unroll
    for (int n = 0; n < 8; n++)
        #pragma unroll
        for (int j = 0; j < 4; j++) oacc[n][j] = 0.0f;
    float eacc = 0.0f;

    __syncthreads();
    {
        const size_t tn = (size_t)tile_k0*16384;
        #pragma unroll
        for (int i = 0; i < 4; i++) {
            uint32_t off = (uint32_t)(i*4096 + tid*16);
            cpa16(smb + OBUF + off,         (const char*)g_khi  + tn + off);
            cpa16(smb + OBUF + 16384 + off, (const char*)g_klo  + tn + off);
            cpa16(smb + OBUF + 32768 + off, (const char*)g_vthi + tn + off);
            cpa16(smb + OBUF + 49152 + off, (const char*)g_vtlo + tn + off);
        }
        CPA_COMMIT();
    }

    for (int c = 0; c < TSEQ/128; c++) {
        __syncthreads();
        if (c < TSEQ/128 - 1) {
            const size_t tn = (size_t)(tile_k0 + c + 1)*16384;
            const uint32_t dst = smb + OBUF + (uint32_t)(((c+1)&1)*65536);
            #pragma unroll
            for (int i = 0; i < 4; i++) {
                uint32_t off = (uint32_t)(i*4096 + tid*16);
                cpa16(dst + off,         (const char*)g_khi  + tn + off);
                cpa16(dst + 16384 + off, (const char*)g_klo  + tn + off);
                cpa16(dst + 32768 + off, (const char*)g_vthi + tn + off);
                cpa16(dst + 49152 + off, (const char*)g_vtlo + tn + off);
            }
            CPA_COMMIT();
            CPA_WAIT1();
        } else {
            CPA_WAIT0();
        }
        __syncthreads();

        const uint32_t kb32 = smb + OBUF + (uint32_t)((c&1)*65536);
        const uint32_t vb32 = kb32 + 32768;

        // ---- S = Q K^T (3-term), ldmatrix ----
        float sacc[16][4];
        #pragma unroll
        for (int n = 0; n < 16; n++)
            #pragma unroll
            for (int j = 0; j < 4; j++) sacc[n][j] = 0.0f;

        #pragma unroll
        for (int ntp = 0; ntp < 8; ntp++) {
            const uint32_t rowb = kb32 + (uint32_t)((ntp*16 + rip)*128);
            #pragma unroll
            for (int ks = 0; ks < 4; ks++) {
                uint32_t co = ((uint32_t)(ks*32) | khb) ^ swl;
                uint32_t bh[4], bl[4];
                ldsm4(bh, rowb + co);
                ldsm4(bl, rowb + 16384 + co);
                mma16816(sacc[2*ntp],   qh[ks], bh[0], bh[1]);
                mma16816(sacc[2*ntp],   qh[ks], bl[0], bl[1]);
                mma16816(sacc[2*ntp],   ql[ks], bh[0], bh[1]);
                mma16816(sacc[2*ntp+1], qh[ks], bh[2], bh[3]);
                mma16816(sacc[2*ntp+1], qh[ks], bl[2], bl[3]);
                mma16816(sacc[2*ntp+1], ql[ks], bh[2], bh[3]);
            }
        }

        // ---- normalized exp, entropy, attn store, P frags ----
        uint32_t ph[8][4], pl[8][4];
        float* arow0 = attn + (rowg + wr + g)*TSEQ + c*128 + 2*tq;
        float* arow1 = arow0 + (size_t)8*TSEQ;
        #pragma unroll
        for (int ks = 0; ks < 8; ks++) {
            #pragma unroll
            for (int h2 = 0; h2 < 2; h2++) {
                int nt = 2*ks + h2;
                float t0 = sacc[nt][0] - lz0, t1 = sacc[nt][1] - lz0;
                float t2 = sacc[nt][2] - lz1, t3 = sacc[nt][3] - lz1;
                float e0 = ex2f_(t0), e1 = ex2f_(t1), e2 = ex2f_(t2), e3 = ex2f_(t3);
                eacc += (e0*t0 + e1*t1) + (e2*t2 + e3*t3);
                *(float2*)(arow0 + nt*8) = make_float2(e0, e1);
                *(float2*)(arow1 + nt*8) = make_float2(e2, e3);
                uint32_t u01 = pk2(e0, e1), u23 = pk2(e2, e3);
                if (h2 == 0) {
                    ph[ks][0] = u01;                 ph[ks][1] = u23;
                    pl[ks][0] = pk2lo(e0, e1, u01);  pl[ks][1] = pk2lo(e2, e3, u23);
                } else {
                    ph[ks][2] = u01;                 ph[ks][3] = u23;
                    pl[ks][2] = pk2lo(e0, e1, u01);  pl[ks][3] = pk2lo(e2, e3, u23);
                }
            }
        }

        // ---- O += P V (ldmatrix on VT, 256B rows) ----
        #pragma unroll
        for (int ntp = 0; ntp < 4; ntp++) {
            const uint32_t rowb = vb32 + (uint32_t)((ntp*16 + rip)*256);
            #pragma unroll
            for (int ks = 0; ks < 8; ks++) {
                uint32_t kb = (uint32_t)(ks*32) | khb;
                uint32_t co = (kb & 128u) + ((kb & 127u) ^ swl);
                uint32_t vh[4], vl[4];
                ldsm4(vh, rowb + co);
                ldsm4(vl, rowb + 16384 + co);
                mma16816(oacc[2*ntp],   ph[ks], vh[0], vh[1]);
                mma16816(oacc[2*ntp],   ph[ks], vl[0], vl[1]);
                mma16816(oacc[2*ntp],   pl[ks], vh[0], vh[1]);
                mma16816(oacc[2*ntp+1], ph[ks], vh[2], vh[3]);
                mma16816(oacc[2*ntp+1], ph[ks], vl[2], vl[3]);
                mma16816(oacc[2*ntp+1], pl[ks], vh[2], vh[3]);
            }
        }
    }

    float* orow0 = out + (rowg + wr + g)*HDIM + 2*tq;
    float* orow1 = orow0 + (size_t)8*HDIM;
    #pragma unroll
    for (int nt = 0; nt < 8; nt++) {
        *(float2*)(orow0 + nt*8) = make_float2(oacc[nt][0], oacc[nt][1]);
        *(float2*)(orow1 + nt*8) = make_float2(oacc[nt][2], oacc[nt][3]);
    }

    #pragma unroll
    for (int off = 16; off > 0; off >>= 1)
        eacc += __shfl_xor_sync(0xffffffffu, eacc, off);
    if (lane == 0) s_ent[w] = eacc;
    __syncthreads();
    if (tid == 0) {
        float t = 0.0f;
        #pragma unroll
        for (int i = 0; i < 8; i++) t += s_ent[i];
        atomicAdd(&g_ent, t);
    }
}

// ---------------------------------------------------------------------------
// K3: finalize energy EMA.  H_mean = -ln2 * g_ent / NROWS
// ---------------------------------------------------------------------------
__global__ void fin_kernel(const float* __restrict__ energy, float* __restrict__ eout)
{
    float ent_mean = -0.6931471805599453f * g_ent / (float)NROWS;
    *eout = 0.9f * energy[0] + 0.1f * ent_mean;
}

// ---------------------------------------------------------------------------
extern "C" void kernel_launch(void* const* d_in, const int* in_sizes, int n_in,
                              void* d_out, int out_size)
{
    const float* x      = (const float*)d_in[0];
    const float* Wq     = (const float*)d_in[1];
    const float* Wk     = (const float*)d_in[2];
    const float* Wv     = (const float*)d_in[3];
    const float* energy = (const float*)d_in[4];

    float* out  = (float*)d_out;                               // [B,T,H]
    float* attn = out + (size_t)BATCH*TSEQ*HDIM;               // [B,T,T]
    float* eout = attn + (size_t)BATCH*TSEQ*TSEQ;              // scalar

    cudaFuncSetAttribute(proj_kernel,  cudaFuncAttributeMaxDynamicSharedMemorySize, SMEM_PROJ);
    cudaFuncSetAttribute(attn2_kernel, cudaFuncAttributeMaxDynamicSharedMemorySize, SMEM_ATTN);

    proj_kernel<<<NTILE, 256, SMEM_PROJ>>>(x, Wq, Wk, Wv);
    attn2_kernel<<<dim3(TSEQ/128, BATCH), 256, SMEM_ATTN>>>(attn, out);
    fin_kernel<<<1, 1>>>(energy, eout);
}